// round 1
// baseline (speedup 1.0000x reference)
#include <cuda_runtime.h>
#include <math.h>

// Problem constants
#define BB   4
#define LL   2048
#define EE   7
#define DD   512
#define HH   8
#define DHH  64
#define PP   720
#define NLL  2
#define UU   40
#define BL   (BB*LL)          // 8192 rows
#define SCALE 0.125f          // 1/sqrt(64)

// ---------------- scratch (device globals; no allocation allowed) ----------
__device__ float g_h[BL*DD];
__device__ float g_q[BL*DD];
__device__ float g_k[BL*DD];
__device__ float g_v[BL*DD];
__device__ float g_ctx[BL*DD];
__device__ float g_t1[BL*DD];
__device__ float g_t2[BL*DD];
__device__ float g_M[BB*HH*LL];
__device__ float g_vmean[BB*DD];
__device__ int   g_topk[BB*HH*UU];

// ---------------- embedding: h = x @ emb_w + emb_b -------------------------
__global__ void embed_kernel(const float* __restrict__ x,
                             const float* __restrict__ w,
                             const float* __restrict__ b) {
    int row = blockIdx.x;                       // 0..BL-1
    int d   = blockIdx.y * 256 + threadIdx.x;   // 0..511
    __shared__ float xs[EE];
    if (threadIdx.x < EE) xs[threadIdx.x] = x[row*EE + threadIdx.x];
    __syncthreads();
    float acc = b[d];
#pragma unroll
    for (int e = 0; e < EE; e++) acc += xs[e] * w[e*DD + d];
    g_h[(size_t)row*DD + d] = acc;
}

// ---------------- SGEMM: C[M,512] = A[M,512] @ W[512,512] + bias (opt relu)
// 128x128x8 tiles, 256 threads, 8x8 per thread.
template <bool RELU>
__global__ void __launch_bounds__(256) gemm_kernel(const float* __restrict__ A,
                                                   const float* __restrict__ W,
                                                   const float* __restrict__ bias,
                                                   float* __restrict__ C) {
    __shared__ float As[8][128];
    __shared__ float Bs[8][128];
    int t  = threadIdx.x;
    int tx = t & 15, ty = t >> 4;
    int m0 = blockIdx.y * 128;
    int n0 = blockIdx.x * 128;

    float acc[8][8];
#pragma unroll
    for (int i = 0; i < 8; i++)
#pragma unroll
        for (int j = 0; j < 8; j++) acc[i][j] = 0.f;

    int arow = t >> 1, ac4 = (t & 1) * 4;   // A: 128 rows x 8 cols, 1 float4/thread
    int brow = t >> 5, bc  = (t & 31) * 4;  // B: 8 rows x 128 cols, 1 float4/thread

    for (int k0 = 0; k0 < DD; k0 += 8) {
        float4 av = *(const float4*)&A[(size_t)(m0 + arow)*DD + k0 + ac4];
        As[ac4+0][arow] = av.x; As[ac4+1][arow] = av.y;
        As[ac4+2][arow] = av.z; As[ac4+3][arow] = av.w;
        *(float4*)&Bs[brow][bc] = *(const float4*)&W[(size_t)(k0 + brow)*DD + n0 + bc];
        __syncthreads();
#pragma unroll
        for (int kk = 0; kk < 8; kk++) {
            float fa[8], fb[8];
            *(float4*)&fa[0] = *(const float4*)&As[kk][ty*8];
            *(float4*)&fa[4] = *(const float4*)&As[kk][ty*8 + 4];
            *(float4*)&fb[0] = *(const float4*)&Bs[kk][tx*8];
            *(float4*)&fb[4] = *(const float4*)&Bs[kk][tx*8 + 4];
#pragma unroll
            for (int i = 0; i < 8; i++)
#pragma unroll
                for (int j = 0; j < 8; j++) acc[i][j] += fa[i]*fb[j];
        }
        __syncthreads();
    }

#pragma unroll
    for (int i = 0; i < 8; i++) {
        int m = m0 + ty*8 + i;
#pragma unroll
        for (int j = 0; j < 8; j += 4) {
            int n = n0 + tx*8 + j;
            float4 o;
            o.x = acc[i][j+0] + bias[n+0];
            o.y = acc[i][j+1] + bias[n+1];
            o.z = acc[i][j+2] + bias[n+2];
            o.w = acc[i][j+3] + bias[n+3];
            if (RELU) {
                o.x = fmaxf(o.x, 0.f); o.y = fmaxf(o.y, 0.f);
                o.z = fmaxf(o.z, 0.f); o.w = fmaxf(o.w, 0.f);
            }
            *(float4*)&C[(size_t)m*DD + n] = o;
        }
    }
}

// ---------------- streaming row stats: M = SCALE*(max(qk) - sum(qk)/L) ----
// One block: 128 queries of one (b,h); loops over all 16 key tiles of 128.
__global__ void __launch_bounds__(256) mstats_kernel() {
    extern __shared__ float sm[];
    float* Qs  = sm;                 // [64][128]  q tile, dh-major
    float* Ks  = sm + 64*128;        // [64][128]  k tile, dh-major
    float* red = sm + 2*64*128;      // 2 * [128][17]

    int t  = threadIdx.x;
    int tx = t & 15, ty = t >> 4;
    int bh = blockIdx.y;             // 0..31
    int b  = bh >> 3, h = bh & 7;
    int q0 = blockIdx.x * 128;

    const float* qbase = g_q + (size_t)b*LL*DD + h*DHH;
    const float* kbase = g_k + (size_t)b*LL*DD + h*DHH;

    // load full Q tile [128 q][64 dh] transposed into Qs[dh][q]
#pragma unroll
    for (int i = 0; i < 8; i++) {
        int idx = i*256 + t;                 // float4 units, 2048 total
        int row = idx >> 4;
        int c4  = (idx & 15) * 4;
        float4 v = *(const float4*)&qbase[(size_t)(q0 + row)*DD + c4];
        Qs[(c4+0)*128 + row] = v.x; Qs[(c4+1)*128 + row] = v.y;
        Qs[(c4+2)*128 + row] = v.z; Qs[(c4+3)*128 + row] = v.w;
    }

    float lmax[8], lsum[8];
#pragma unroll
    for (int i = 0; i < 8; i++) { lmax[i] = -INFINITY; lsum[i] = 0.f; }

    for (int nt = 0; nt < LL/128; nt++) {
        __syncthreads();                 // Ks reuse guard (also covers Qs 1st iter)
        int n0 = nt * 128;
#pragma unroll
        for (int i = 0; i < 8; i++) {
            int idx = i*256 + t;
            int row = idx >> 4;
            int c4  = (idx & 15) * 4;
            float4 v = *(const float4*)&kbase[(size_t)(n0 + row)*DD + c4];
            Ks[(c4+0)*128 + row] = v.x; Ks[(c4+1)*128 + row] = v.y;
            Ks[(c4+2)*128 + row] = v.z; Ks[(c4+3)*128 + row] = v.w;
        }
        __syncthreads();

        float acc[8][8];
#pragma unroll
        for (int i = 0; i < 8; i++)
#pragma unroll
            for (int j = 0; j < 8; j++) acc[i][j] = 0.f;

#pragma unroll 8
        for (int kk = 0; kk < DHH; kk++) {
            float fa[8], fb[8];
            *(float4*)&fa[0] = *(const float4*)&Qs[kk*128 + ty*8];
            *(float4*)&fa[4] = *(const float4*)&Qs[kk*128 + ty*8 + 4];
            *(float4*)&fb[0] = *(const float4*)&Ks[kk*128 + tx*8];
            *(float4*)&fb[4] = *(const float4*)&Ks[kk*128 + tx*8 + 4];
#pragma unroll
            for (int i = 0; i < 8; i++)
#pragma unroll
                for (int j = 0; j < 8; j++) acc[i][j] += fa[i]*fb[j];
        }
#pragma unroll
        for (int i = 0; i < 8; i++)
#pragma unroll
            for (int j = 0; j < 8; j++) {
                lmax[i] = fmaxf(lmax[i], acc[i][j]);
                lsum[i] += acc[i][j];
            }
    }

    float* redm = red;
    float* reds = red + 128*17;
    __syncthreads();
#pragma unroll
    for (int i = 0; i < 8; i++) {
        redm[(ty*8 + i)*17 + tx] = lmax[i];
        reds[(ty*8 + i)*17 + tx] = lsum[i];
    }
    __syncthreads();
    if (t < 128) {
        float mx = -INFINITY, s = 0.f;
#pragma unroll
        for (int x = 0; x < 16; x++) {
            mx = fmaxf(mx, redm[t*17 + x]);
            s += reds[t*17 + x];
        }
        g_M[(size_t)bh*LL + q0 + t] = SCALE * (mx - s * (1.f/LL));
    }
}

// ---------------- top-U selection per (b,h), JAX tie-break (lower idx) -----
__global__ void topk_kernel() {
    __shared__ float vals[LL];
    __shared__ float rv[256];
    __shared__ int   ri[256];
    int t  = threadIdx.x;
    int bh = blockIdx.x;
    for (int i = t; i < LL; i += 256) vals[i] = g_M[(size_t)bh*LL + i];
    __syncthreads();
    for (int u = 0; u < UU; u++) {
        float bv = -INFINITY; int bi = 0x7fffffff;
        for (int i = t; i < LL; i += 256) {
            float v = vals[i];
            if (v > bv) { bv = v; bi = i; }
        }
        rv[t] = bv; ri[t] = bi;
        __syncthreads();
        for (int s = 128; s > 0; s >>= 1) {
            if (t < s) {
                float ov = rv[t+s]; int oi = ri[t+s];
                if (ov > rv[t] || (ov == rv[t] && oi < ri[t])) { rv[t] = ov; ri[t] = oi; }
            }
            __syncthreads();
        }
        if (t == 0) { g_topk[bh*UU + u] = ri[0]; vals[ri[0]] = -INFINITY; }
        __syncthreads();
    }
}

// ---------------- mean of V over L (partial-sum + atomics) -----------------
__global__ void vmean_zero_kernel() {
    g_vmean[blockIdx.x*256 + threadIdx.x] = 0.f;
}
__global__ void vmean_part_kernel() {
    int d  = blockIdx.x*256 + threadIdx.x;
    int lc = blockIdx.y;
    int b  = blockIdx.z;
    const float* vb = g_v + ((size_t)(b*LL + lc*128))*DD + d;
    float s = 0.f;
#pragma unroll 4
    for (int l = 0; l < 128; l++) s += vb[(size_t)l*DD];
    atomicAdd(&g_vmean[b*DD + d], s);
}
__global__ void ctx_fill_kernel() {
    int row = blockIdx.x;
    int d   = blockIdx.y*256 + threadIdx.x;
    int b   = row >> 11;                 // row / LL
    g_ctx[(size_t)row*DD + d] = g_vmean[b*DD + d] * (1.f/LL);
}

// ---------------- sparse attention for the U active queries ----------------
__global__ void __launch_bounds__(256) attn_kernel() {
    __shared__ float qrow[DHH];
    __shared__ float probs[LL];
    __shared__ float red[256];
    __shared__ float upd4[4][DHH];
    int t  = threadIdx.x;
    int bh = blockIdx.y;
    int b  = bh >> 3, h = bh & 7;
    int u  = blockIdx.x;
    int lq = g_topk[bh*UU + u];

    const float* kbase = g_k + (size_t)b*LL*DD + h*DHH;
    const float* vbase = g_v + (size_t)b*LL*DD + h*DHH;
    if (t < DHH) qrow[t] = g_q[((size_t)b*LL + lq)*DD + h*DHH + t];
    __syncthreads();

    float lmax = -INFINITY;
    float sc[8];
#pragma unroll
    for (int i = 0; i < 8; i++) {
        int l = i*256 + t;
        const float* kr = kbase + (size_t)l*DD;
        float s = 0.f;
#pragma unroll
        for (int dh = 0; dh < DHH; dh += 4) {
            float4 kv = *(const float4*)&kr[dh];
            s += qrow[dh+0]*kv.x + qrow[dh+1]*kv.y + qrow[dh+2]*kv.z + qrow[dh+3]*kv.w;
        }
        s *= SCALE;
        sc[i] = s;
        lmax = fmaxf(lmax, s);
    }
    red[t] = lmax; __syncthreads();
    for (int s = 128; s > 0; s >>= 1) { if (t < s) red[t] = fmaxf(red[t], red[t+s]); __syncthreads(); }
    float mx = red[0];
    __syncthreads();

    float lsum = 0.f;
#pragma unroll
    for (int i = 0; i < 8; i++) {
        float e = expf(sc[i] - mx);
        probs[i*256 + t] = e;
        lsum += e;
    }
    red[t] = lsum; __syncthreads();
    for (int s = 128; s > 0; s >>= 1) { if (t < s) red[t] += red[t+s]; __syncthreads(); }
    float denom = red[0];
    __syncthreads();

    int c = t >> 6, dh = t & 63;
    float acc = 0.f;
    for (int l = c*512; l < c*512 + 512; l++)
        acc += probs[l] * vbase[(size_t)l*DD + dh];
    upd4[c][dh] = acc;
    __syncthreads();
    if (t < DHH) {
        float tot = (upd4[0][t] + upd4[1][t] + upd4[2][t] + upd4[3][t]) / denom;
        g_ctx[((size_t)b*LL + lq)*DD + h*DHH + t] = tot;
    }
}

// ---------------- residual + LayerNorm -> g_h ------------------------------
__global__ void lnres_kernel(const float* __restrict__ delta,
                             const float* __restrict__ gam,
                             const float* __restrict__ bet) {
    int row = blockIdx.x;
    int t   = threadIdx.x;
    __shared__ float red[256];
    float v0 = g_h[(size_t)row*DD + t]       + delta[(size_t)row*DD + t];
    float v1 = g_h[(size_t)row*DD + t + 256] + delta[(size_t)row*DD + t + 256];
    red[t] = v0 + v1; __syncthreads();
    for (int s = 128; s > 0; s >>= 1) { if (t < s) red[t] += red[t+s]; __syncthreads(); }
    float mean = red[0] * (1.f/DD);
    __syncthreads();
    float d0 = v0 - mean, d1 = v1 - mean;
    red[t] = d0*d0 + d1*d1; __syncthreads();
    for (int s = 128; s > 0; s >>= 1) { if (t < s) red[t] += red[t+s]; __syncthreads(); }
    float inv = rsqrtf(red[0]*(1.f/DD) + 1e-5f);
    g_h[(size_t)row*DD + t]       = d0*inv*gam[t]     + bet[t];
    g_h[(size_t)row*DD + t + 256] = d1*inv*gam[t+256] + bet[t+256];
}

// ---------------- final projection -----------------------------------------
__global__ void proj_kernel(const float* __restrict__ w,
                            const float* __restrict__ b,
                            float* __restrict__ out) {
    int t  = threadIdx.x;
    int bp = blockIdx.x;                    // 0..B*P-1
    int bb = bp / PP, p = bp % PP;
    int row = bb*LL + (LL - PP) + p;
    float acc[EE];
#pragma unroll
    for (int e = 0; e < EE; e++) acc[e] = 0.f;
    for (int d = t; d < DD; d += 256) {
        float hv = g_h[(size_t)row*DD + d];
#pragma unroll
        for (int e = 0; e < EE; e++) acc[e] += hv * w[d*EE + e];
    }
    __shared__ float red[256];
#pragma unroll
    for (int e = 0; e < EE; e++) {
        red[t] = acc[e]; __syncthreads();
        for (int s = 128; s > 0; s >>= 1) { if (t < s) red[t] += red[t+s]; __syncthreads(); }
        if (t == 0) out[bp*EE + e] = red[0] + b[e];
        __syncthreads();
    }
}

// ---------------- host orchestration ---------------------------------------
extern "C" void kernel_launch(void* const* d_in, const int* in_sizes, int n_in,
                              void* d_out, int out_size) {
    const float* x      = (const float*)d_in[0];
    const float* emb_w  = (const float*)d_in[1];
    const float* emb_b  = (const float*)d_in[2];
    const float* Wq     = (const float*)d_in[3];
    const float* bq     = (const float*)d_in[4];
    const float* Wk     = (const float*)d_in[5];
    const float* bk     = (const float*)d_in[6];
    const float* Wv     = (const float*)d_in[7];
    const float* bv     = (const float*)d_in[8];
    const float* Wo     = (const float*)d_in[9];
    const float* bo     = (const float*)d_in[10];
    const float* W1     = (const float*)d_in[11];
    const float* b1     = (const float*)d_in[12];
    const float* W2     = (const float*)d_in[13];
    const float* b2     = (const float*)d_in[14];
    const float* ln1_g  = (const float*)d_in[15];
    const float* ln1_b  = (const float*)d_in[16];
    const float* ln2_g  = (const float*)d_in[17];
    const float* ln2_b  = (const float*)d_in[18];
    const float* proj_w = (const float*)d_in[19];
    const float* proj_b = (const float*)d_in[20];
    float* out = (float*)d_out;

    float *ph, *pq, *pk, *pv, *pctx, *pt1, *pt2;
    cudaGetSymbolAddress((void**)&ph,   g_h);
    cudaGetSymbolAddress((void**)&pq,   g_q);
    cudaGetSymbolAddress((void**)&pk,   g_k);
    cudaGetSymbolAddress((void**)&pv,   g_v);
    cudaGetSymbolAddress((void**)&pctx, g_ctx);
    cudaGetSymbolAddress((void**)&pt1,  g_t1);
    cudaGetSymbolAddress((void**)&pt2,  g_t2);

    const int MSTATS_SMEM = (2*64*128 + 2*128*17) * 4;   // 82944 B
    cudaFuncSetAttribute(mstats_kernel, cudaFuncAttributeMaxDynamicSharedMemorySize, MSTATS_SMEM);

    dim3 ggrid(DD/128, BL/128);       // (4, 64)

    embed_kernel<<<dim3(BL, DD/256), 256>>>(x, emb_w, emb_b);

    for (int lay = 0; lay < NLL; lay++) {
        const float* lWq = Wq + (size_t)lay*DD*DD;
        const float* lWk = Wk + (size_t)lay*DD*DD;
        const float* lWv = Wv + (size_t)lay*DD*DD;
        const float* lWo = Wo + (size_t)lay*DD*DD;
        const float* lW1 = W1 + (size_t)lay*DD*DD;
        const float* lW2 = W2 + (size_t)lay*DD*DD;

        gemm_kernel<false><<<ggrid, 256>>>(ph, lWq, bq + lay*DD, pq);
        gemm_kernel<false><<<ggrid, 256>>>(ph, lWk, bk + lay*DD, pk);
        gemm_kernel<false><<<ggrid, 256>>>(ph, lWv, bv + lay*DD, pv);

        mstats_kernel<<<dim3(LL/128, BB*HH), 256, MSTATS_SMEM>>>();
        topk_kernel<<<BB*HH, 256>>>();

        vmean_zero_kernel<<<BB*DD/256, 256>>>();
        vmean_part_kernel<<<dim3(DD/256, LL/128, BB), 256>>>();
        ctx_fill_kernel<<<dim3(BL, DD/256), 256>>>();
        attn_kernel<<<dim3(UU, BB*HH), 256>>>();

        gemm_kernel<false><<<ggrid, 256>>>(pctx, lWo, bo + lay*DD, pt1);
        lnres_kernel<<<BL, 256>>>(pt1, ln1_g + lay*DD, ln1_b + lay*DD);

        gemm_kernel<true ><<<ggrid, 256>>>(ph, lW1, b1 + lay*DD, pt1);
        gemm_kernel<false><<<ggrid, 256>>>(pt1, lW2, b2 + lay*DD, pt2);
        lnres_kernel<<<BL, 256>>>(pt2, ln2_g + lay*DD, ln2_b + lay*DD);
    }

    proj_kernel<<<BB*PP, 256>>>(proj_w, proj_b, out);
}

// round 3
// speedup vs baseline: 2.2401x; 2.2401x over previous
#include <cuda_runtime.h>
#include <math.h>
#include <cstdint>

// Problem constants
#define BB   4
#define LL   2048
#define EE   7
#define DD   512
#define HH   8
#define DHH  64
#define PP   720
#define NLL  2
#define UU   40
#define BL   (BB*LL)          // 8192 rows
#define SCALE 0.125f          // 1/sqrt(64)

// ---------------- scratch (device globals; no allocation allowed) ----------
__device__ float g_h[BL*DD];
__device__ float g_q[BL*DD];
__device__ float g_k[BL*DD];
__device__ float g_v[BL*DD];
__device__ float g_ctx[BL*DD];
__device__ float g_t1[BL*DD];
__device__ float g_t2[BL*DD];
__device__ float g_M[BB*HH*LL];
__device__ float g_vmean[BB*DD];
__device__ int   g_topk[BB*HH*UU];
__device__ float g_wt[12*DD*DD];       // transposed weights, [n][k]

// ---------------- tf32 helpers ---------------------------------------------
__device__ __forceinline__ float totf32(float x) {
    uint32_t r;
    asm("cvt.rna.tf32.f32 %0, %1;" : "=r"(r) : "f"(x));
    return __uint_as_float(r);
}
__device__ __forceinline__ void mma_tf32(float c[4], const uint32_t a[4], const uint32_t b[2]) {
    asm volatile("mma.sync.aligned.m16n8k8.row.col.f32.tf32.tf32.f32 "
        "{%0,%1,%2,%3}, {%4,%5,%6,%7}, {%8,%9}, {%0,%1,%2,%3};"
        : "+f"(c[0]), "+f"(c[1]), "+f"(c[2]), "+f"(c[3])
        : "r"(a[0]), "r"(a[1]), "r"(a[2]), "r"(a[3]), "r"(b[0]), "r"(b[1]));
}

// ---------------- weight transpose: Wt[n][k] = W[k][n] ---------------------
__global__ void transpose_kernel(const float* __restrict__ W, float* __restrict__ Wt) {
    __shared__ float tile[32][33];
    int x0 = blockIdx.x*32, y0 = blockIdx.y*32;
    int tx = threadIdx.x, ty = threadIdx.y;   // (32,8)
#pragma unroll
    for (int j = 0; j < 32; j += 8)
        tile[ty+j][tx] = W[(size_t)(y0+ty+j)*DD + x0+tx];
    __syncthreads();
#pragma unroll
    for (int j = 0; j < 32; j += 8)
        Wt[(size_t)(x0+ty+j)*DD + y0+tx] = tile[tx][ty+j];
}

// ---------------- embedding: h = x @ emb_w + emb_b -------------------------
__global__ void embed_kernel(const float* __restrict__ x,
                             const float* __restrict__ w,
                             const float* __restrict__ b) {
    int row = blockIdx.x;
    int d   = blockIdx.y * 256 + threadIdx.x;
    __shared__ float xs[EE];
    if (threadIdx.x < EE) xs[threadIdx.x] = x[row*EE + threadIdx.x];
    __syncthreads();
    float acc = b[d];
#pragma unroll
    for (int e = 0; e < EE; e++) acc += xs[e] * w[e*DD + d];
    g_h[(size_t)row*DD + d] = acc;
}

// =============== tf32 mma.sync GEMM: C = A @ Wt^T + bias (opt relu) ========
// A[8192,512] K-major, Bt[512,512] = W^T ([N,K] K-major).
// CTA 128x128, 8 warps (2 m x 4 n), warp tile 64x32 of m16n8k8 atoms.
// K in 16 chunks of 32, double-buffered SMEM (pad 36 -> conflict-free frags).
#define GPAD 36
#define GBUF (128*GPAD)
__global__ void __launch_bounds__(256) gemm_mma(const float* __restrict__ A,
                                                const float* __restrict__ Bt,
                                                const float* __restrict__ bias,
                                                float* __restrict__ C, int relu) {
    extern __shared__ float sm[];
    float* As = sm;                 // [2][GBUF]
    float* Bs = sm + 2*GBUF;        // [2][GBUF]

    int t = threadIdx.x, w = t >> 5, l = t & 31;
    int g = l >> 2, tig = l & 3;
    int wm = w >> 2, wn = w & 3;
    int m0 = blockIdx.y * 128, n0 = blockIdx.x * 128;

    const float* Ab = A  + (size_t)m0 * DD;
    const float* Bb = Bt + (size_t)n0 * DD;

    float c[4][4][4];
#pragma unroll
    for (int i = 0; i < 4; i++)
#pragma unroll
        for (int j = 0; j < 4; j++)
#pragma unroll
            for (int r = 0; r < 4; r++) c[i][j][r] = 0.f;

    int lrow = t >> 3;            // 0..31 -> row within 128 handled per r-step
    int lc4  = (t & 7) * 4;       // col 0..28

    float4 aL[4], bL[4];
    // prologue: load chunk 0
#pragma unroll
    for (int r = 0; r < 4; r++) {
        int row = r*32 + lrow;
        aL[r] = *(const float4*)(Ab + (size_t)row*DD + lc4);
        bL[r] = *(const float4*)(Bb + (size_t)row*DD + lc4);
    }
#pragma unroll
    for (int r = 0; r < 4; r++) {
        int row = r*32 + lrow;
        As[row*GPAD + lc4+0] = totf32(aL[r].x); As[row*GPAD + lc4+1] = totf32(aL[r].y);
        As[row*GPAD + lc4+2] = totf32(aL[r].z); As[row*GPAD + lc4+3] = totf32(aL[r].w);
        Bs[row*GPAD + lc4+0] = totf32(bL[r].x); Bs[row*GPAD + lc4+1] = totf32(bL[r].y);
        Bs[row*GPAD + lc4+2] = totf32(bL[r].z); Bs[row*GPAD + lc4+3] = totf32(bL[r].w);
    }
    __syncthreads();

    for (int chunk = 0; chunk < 16; chunk++) {
        int p = chunk & 1;
        if (chunk < 15) {
            int k0 = (chunk + 1) * 32;
#pragma unroll
            for (int r = 0; r < 4; r++) {
                int row = r*32 + lrow;
                aL[r] = *(const float4*)(Ab + (size_t)row*DD + k0 + lc4);
                bL[r] = *(const float4*)(Bb + (size_t)row*DD + k0 + lc4);
            }
        }
        const float* Ap = As + p*GBUF;
        const float* Bp = Bs + p*GBUF;
#pragma unroll
        for (int kk = 0; kk < 4; kk++) {
            int kb = kk * 8;
            uint32_t af[4][4];
#pragma unroll
            for (int mt = 0; mt < 4; mt++) {
                int base = (wm*64 + mt*16 + g)*GPAD + kb + tig;
                af[mt][0] = __float_as_uint(Ap[base]);
                af[mt][1] = __float_as_uint(Ap[base + 8*GPAD]);
                af[mt][2] = __float_as_uint(Ap[base + 4]);
                af[mt][3] = __float_as_uint(Ap[base + 8*GPAD + 4]);
            }
            uint32_t bf[4][2];
#pragma unroll
            for (int nt = 0; nt < 4; nt++) {
                int base = (wn*32 + nt*8 + g)*GPAD + kb + tig;
                bf[nt][0] = __float_as_uint(Bp[base]);
                bf[nt][1] = __float_as_uint(Bp[base + 4]);
            }
#pragma unroll
            for (int mt = 0; mt < 4; mt++)
#pragma unroll
                for (int nt = 0; nt < 4; nt++)
                    mma_tf32(c[mt][nt], af[mt], bf[nt]);
        }
        __syncthreads();
        if (chunk < 15) {
            float* Ad = As + (p^1)*GBUF;
            float* Bd = Bs + (p^1)*GBUF;
#pragma unroll
            for (int r = 0; r < 4; r++) {
                int row = r*32 + lrow;
                Ad[row*GPAD + lc4+0] = totf32(aL[r].x); Ad[row*GPAD + lc4+1] = totf32(aL[r].y);
                Ad[row*GPAD + lc4+2] = totf32(aL[r].z); Ad[row*GPAD + lc4+3] = totf32(aL[r].w);
                Bd[row*GPAD + lc4+0] = totf32(bL[r].x); Bd[row*GPAD + lc4+1] = totf32(bL[r].y);
                Bd[row*GPAD + lc4+2] = totf32(bL[r].z); Bd[row*GPAD + lc4+3] = totf32(bL[r].w);
            }
            __syncthreads();
        }
    }

    // epilogue: bias (+relu), direct float2 stores
#pragma unroll
    for (int mt = 0; mt < 4; mt++) {
        int row = m0 + wm*64 + mt*16 + g;
#pragma unroll
        for (int nt = 0; nt < 4; nt++) {
            int col = n0 + wn*32 + nt*8 + 2*tig;
            float b0 = bias[col], b1 = bias[col+1];
            float2 v0 = make_float2(c[mt][nt][0] + b0, c[mt][nt][1] + b1);
            float2 v1 = make_float2(c[mt][nt][2] + b0, c[mt][nt][3] + b1);
            if (relu) {
                v0.x = fmaxf(v0.x, 0.f); v0.y = fmaxf(v0.y, 0.f);
                v1.x = fmaxf(v1.x, 0.f); v1.y = fmaxf(v1.y, 0.f);
            }
            *(float2*)(C + (size_t)row*DD + col)     = v0;
            *(float2*)(C + (size_t)(row+8)*DD + col) = v1;
        }
    }
}

// ========= tf32 mma.sync score stats: M = SCALE*(max - mean) ===============
// One CTA per (q-tile 128, bh). Q tile resident; loop 16 key tiles of 128.
#define QPAD 68
#define QTILE (128*QPAD)
__global__ void __launch_bounds__(256) mstats_mma() {
    extern __shared__ float sm[];
    float* Qs   = sm;               // [128][QPAD]
    float* Ks   = sm + QTILE;       // [128][QPAD]
    float* redm = sm + 2*QTILE;     // [4][128]
    float* reds = sm + 2*QTILE + 512;

    int t = threadIdx.x, w = t >> 5, l = t & 31;
    int g = l >> 2, tig = l & 3;
    int wm = w >> 2, wn = w & 3;
    int bh = blockIdx.y, b = bh >> 3, h = bh & 7;
    int q0 = blockIdx.x * 128;

    const float* qb = g_q + (size_t)b*LL*DD + h*DHH;
    const float* kb = g_k + (size_t)b*LL*DD + h*DHH;

    int lrow = t >> 4;            // 0..15
    int lc4  = (t & 15) * 4;      // col 0..60

    // load Q tile [128][64]
#pragma unroll
    for (int r = 0; r < 8; r++) {
        int row = r*16 + lrow;
        float4 v = *(const float4*)(qb + (size_t)(q0 + row)*DD + lc4);
        Qs[row*QPAD + lc4+0] = totf32(v.x); Qs[row*QPAD + lc4+1] = totf32(v.y);
        Qs[row*QPAD + lc4+2] = totf32(v.z); Qs[row*QPAD + lc4+3] = totf32(v.w);
    }

    float mx[8], sum[8];
#pragma unroll
    for (int s = 0; s < 8; s++) { mx[s] = -INFINITY; sum[s] = 0.f; }

    for (int ntile = 0; ntile < 16; ntile++) {
        int n0 = ntile * 128;
#pragma unroll
        for (int r = 0; r < 8; r++) {
            int row = r*16 + lrow;
            float4 v = *(const float4*)(kb + (size_t)(n0 + row)*DD + lc4);
            Ks[row*QPAD + lc4+0] = totf32(v.x); Ks[row*QPAD + lc4+1] = totf32(v.y);
            Ks[row*QPAD + lc4+2] = totf32(v.z); Ks[row*QPAD + lc4+3] = totf32(v.w);
        }
        __syncthreads();

        float c[4][4][4];
#pragma unroll
        for (int i = 0; i < 4; i++)
#pragma unroll
            for (int j = 0; j < 4; j++)
#pragma unroll
                for (int r = 0; r < 4; r++) c[i][j][r] = 0.f;

#pragma unroll
        for (int kk = 0; kk < 8; kk++) {
            int kbs = kk * 8;
            uint32_t af[4][4];
#pragma unroll
            for (int mt = 0; mt < 4; mt++) {
                int base = (wm*64 + mt*16 + g)*QPAD + kbs + tig;
                af[mt][0] = __float_as_uint(Qs[base]);
                af[mt][1] = __float_as_uint(Qs[base + 8*QPAD]);
                af[mt][2] = __float_as_uint(Qs[base + 4]);
                af[mt][3] = __float_as_uint(Qs[base + 8*QPAD + 4]);
            }
            uint32_t bf[4][2];
#pragma unroll
            for (int nt = 0; nt < 4; nt++) {
                int base = (wn*32 + nt*8 + g)*QPAD + kbs + tig;
                bf[nt][0] = __float_as_uint(Ks[base]);
                bf[nt][1] = __float_as_uint(Ks[base + 4]);
            }
#pragma unroll
            for (int mt = 0; mt < 4; mt++)
#pragma unroll
                for (int nt = 0; nt < 4; nt++)
                    mma_tf32(c[mt][nt], af[mt], bf[nt]);
        }

#pragma unroll
        for (int mt = 0; mt < 4; mt++)
#pragma unroll
            for (int nt = 0; nt < 4; nt++) {
                mx[mt*2+0]  = fmaxf(mx[mt*2+0], fmaxf(c[mt][nt][0], c[mt][nt][1]));
                sum[mt*2+0] += c[mt][nt][0] + c[mt][nt][1];
                mx[mt*2+1]  = fmaxf(mx[mt*2+1], fmaxf(c[mt][nt][2], c[mt][nt][3]));
                sum[mt*2+1] += c[mt][nt][2] + c[mt][nt][3];
            }
        __syncthreads();
    }

    // reduce across tig lanes (share rows)
#pragma unroll
    for (int s = 0; s < 8; s++) {
        mx[s]  = fmaxf(mx[s],  __shfl_xor_sync(0xffffffff, mx[s], 1));
        mx[s]  = fmaxf(mx[s],  __shfl_xor_sync(0xffffffff, mx[s], 2));
        sum[s] += __shfl_xor_sync(0xffffffff, sum[s], 1);
        sum[s] += __shfl_xor_sync(0xffffffff, sum[s], 2);
    }
    if (tig == 0) {
#pragma unroll
        for (int mt = 0; mt < 4; mt++)
#pragma unroll
            for (int hi = 0; hi < 2; hi++) {
                int row = wm*64 + mt*16 + g + hi*8;
                redm[wn*128 + row] = mx[mt*2+hi];
                reds[wn*128 + row] = sum[mt*2+hi];
            }
    }
    __syncthreads();
    if (t < 128) {
        float m = redm[t], s = reds[t];
#pragma unroll
        for (int x = 1; x < 4; x++) {
            m = fmaxf(m, redm[x*128 + t]);
            s += reds[x*128 + t];
        }
        g_M[(size_t)bh*LL + q0 + t] = SCALE * (m - s * (1.f/LL));
    }
}

// ---------------- top-U selection per (b,h), JAX tie-break (lower idx) -----
__global__ void topk_kernel() {
    __shared__ float vals[LL];
    __shared__ float rv[256];
    __shared__ int   ri[256];
    int t  = threadIdx.x;
    int bh = blockIdx.x;
    for (int i = t; i < LL; i += 256) vals[i] = g_M[(size_t)bh*LL + i];
    __syncthreads();
    for (int u = 0; u < UU; u++) {
        float bv = -INFINITY; int bi = 0x7fffffff;
        for (int i = t; i < LL; i += 256) {
            float v = vals[i];
            if (v > bv) { bv = v; bi = i; }
        }
        rv[t] = bv; ri[t] = bi;
        __syncthreads();
        for (int s = 128; s > 0; s >>= 1) {
            if (t < s) {
                float ov = rv[t+s]; int oi = ri[t+s];
                if (ov > rv[t] || (ov == rv[t] && oi < ri[t])) { rv[t] = ov; ri[t] = oi; }
            }
            __syncthreads();
        }
        if (t == 0) { g_topk[bh*UU + u] = ri[0]; vals[ri[0]] = -INFINITY; }
        __syncthreads();
    }
}

// ---------------- mean of V over L (partial-sum + atomics) -----------------
__global__ void vmean_zero_kernel() {
    g_vmean[blockIdx.x*256 + threadIdx.x] = 0.f;
}
__global__ void vmean_part_kernel() {
    int d  = blockIdx.x*256 + threadIdx.x;
    int lc = blockIdx.y;
    int b  = blockIdx.z;
    const float* vb = g_v + ((size_t)(b*LL + lc*128))*DD + d;
    float s = 0.f;
#pragma unroll 4
    for (int l = 0; l < 128; l++) s += vb[(size_t)l*DD];
    atomicAdd(&g_vmean[b*DD + d], s);
}
__global__ void ctx_fill_kernel() {
    int row = blockIdx.x;
    int d   = blockIdx.y*256 + threadIdx.x;
    int b   = row >> 11;
    g_ctx[(size_t)row*DD + d] = g_vmean[b*DD + d] * (1.f/LL);
}

// ---------------- sparse attention for the U active queries ----------------
__global__ void __launch_bounds__(256) attn_kernel() {
    __shared__ float qrow[DHH];
    __shared__ float probs[LL];
    __shared__ float red[256];
    __shared__ float upd4[4][DHH];
    int t  = threadIdx.x;
    int bh = blockIdx.y;
    int b  = bh >> 3, h = bh & 7;
    int u  = blockIdx.x;
    int lq = g_topk[bh*UU + u];

    const float* kbase = g_k + (size_t)b*LL*DD + h*DHH;
    const float* vbase = g_v + (size_t)b*LL*DD + h*DHH;
    if (t < DHH) qrow[t] = g_q[((size_t)b*LL + lq)*DD + h*DHH + t];
    __syncthreads();

    float lmax = -INFINITY;
    float sc[8];
#pragma unroll
    for (int i = 0; i < 8; i++) {
        int l = i*256 + t;
        const float* kr = kbase + (size_t)l*DD;
        float s = 0.f;
#pragma unroll
        for (int dh = 0; dh < DHH; dh += 4) {
            float4 kv = *(const float4*)&kr[dh];
            s += qrow[dh+0]*kv.x + qrow[dh+1]*kv.y + qrow[dh+2]*kv.z + qrow[dh+3]*kv.w;
        }
        s *= SCALE;
        sc[i] = s;
        lmax = fmaxf(lmax, s);
    }
    red[t] = lmax; __syncthreads();
    for (int s = 128; s > 0; s >>= 1) { if (t < s) red[t] = fmaxf(red[t], red[t+s]); __syncthreads(); }
    float mx = red[0];
    __syncthreads();

    float lsum = 0.f;
#pragma unroll
    for (int i = 0; i < 8; i++) {
        float e = expf(sc[i] - mx);
        probs[i*256 + t] = e;
        lsum += e;
    }
    red[t] = lsum; __syncthreads();
    for (int s = 128; s > 0; s >>= 1) { if (t < s) red[t] += red[t+s]; __syncthreads(); }
    float denom = red[0];
    __syncthreads();

    int c = t >> 6, dh = t & 63;
    float acc = 0.f;
    for (int l = c*512; l < c*512 + 512; l++)
        acc += probs[l] * vbase[(size_t)l*DD + dh];
    upd4[c][dh] = acc;
    __syncthreads();
    if (t < DHH) {
        float tot = (upd4[0][t] + upd4[1][t] + upd4[2][t] + upd4[3][t]) / denom;
        g_ctx[((size_t)b*LL + lq)*DD + h*DHH + t] = tot;
    }
}

// ---------------- residual + LayerNorm -> g_h ------------------------------
__global__ void lnres_kernel(const float* __restrict__ delta,
                             const float* __restrict__ gam,
                             const float* __restrict__ bet) {
    int row = blockIdx.x;
    int t   = threadIdx.x;
    __shared__ float red[256];
    float v0 = g_h[(size_t)row*DD + t]       + delta[(size_t)row*DD + t];
    float v1 = g_h[(size_t)row*DD + t + 256] + delta[(size_t)row*DD + t + 256];
    red[t] = v0 + v1; __syncthreads();
    for (int s = 128; s > 0; s >>= 1) { if (t < s) red[t] += red[t+s]; __syncthreads(); }
    float mean = red[0] * (1.f/DD);
    __syncthreads();
    float d0 = v0 - mean, d1 = v1 - mean;
    red[t] = d0*d0 + d1*d1; __syncthreads();
    for (int s = 128; s > 0; s >>= 1) { if (t < s) red[t] += red[t+s]; __syncthreads(); }
    float inv = rsqrtf(red[0]*(1.f/DD) + 1e-5f);
    g_h[(size_t)row*DD + t]       = d0*inv*gam[t]     + bet[t];
    g_h[(size_t)row*DD + t + 256] = d1*inv*gam[t+256] + bet[t+256];
}

// ---------------- final projection -----------------------------------------
__global__ void proj_kernel(const float* __restrict__ w,
                            const float* __restrict__ b,
                            float* __restrict__ out) {
    int t  = threadIdx.x;
    int bp = blockIdx.x;
    int bb = bp / PP, p = bp % PP;
    int row = bb*LL + (LL - PP) + p;
    float acc[EE];
#pragma unroll
    for (int e = 0; e < EE; e++) acc[e] = 0.f;
    for (int d = t; d < DD; d += 256) {
        float hv = g_h[(size_t)row*DD + d];
#pragma unroll
        for (int e = 0; e < EE; e++) acc[e] += hv * w[d*EE + e];
    }
    __shared__ float red[256];
#pragma unroll
    for (int e = 0; e < EE; e++) {
        red[t] = acc[e]; __syncthreads();
        for (int s = 128; s > 0; s >>= 1) { if (t < s) red[t] += red[t+s]; __syncthreads(); }
        if (t == 0) out[bp*EE + e] = red[0] + b[e];
        __syncthreads();
    }
}

// ---------------- host orchestration ---------------------------------------
extern "C" void kernel_launch(void* const* d_in, const int* in_sizes, int n_in,
                              void* d_out, int out_size) {
    const float* x      = (const float*)d_in[0];
    const float* emb_w  = (const float*)d_in[1];
    const float* emb_b  = (const float*)d_in[2];
    const float* Wq     = (const float*)d_in[3];
    const float* bq     = (const float*)d_in[4];
    const float* Wk     = (const float*)d_in[5];
    const float* bk     = (const float*)d_in[6];
    const float* Wv     = (const float*)d_in[7];
    const float* bv     = (const float*)d_in[8];
    const float* Wo     = (const float*)d_in[9];
    const float* bo     = (const float*)d_in[10];
    const float* W1     = (const float*)d_in[11];
    const float* b1     = (const float*)d_in[12];
    const float* W2     = (const float*)d_in[13];
    const float* b2     = (const float*)d_in[14];
    const float* ln1_g  = (const float*)d_in[15];
    const float* ln1_b  = (const float*)d_in[16];
    const float* ln2_g  = (const float*)d_in[17];
    const float* ln2_b  = (const float*)d_in[18];
    const float* proj_w = (const float*)d_in[19];
    const float* proj_b = (const float*)d_in[20];
    float* out = (float*)d_out;

    float *ph, *pq, *pk, *pv, *pctx, *pt1, *pt2, *pwt;
    cudaGetSymbolAddress((void**)&ph,   g_h);
    cudaGetSymbolAddress((void**)&pq,   g_q);
    cudaGetSymbolAddress((void**)&pk,   g_k);
    cudaGetSymbolAddress((void**)&pv,   g_v);
    cudaGetSymbolAddress((void**)&pctx, g_ctx);
    cudaGetSymbolAddress((void**)&pt1,  g_t1);
    cudaGetSymbolAddress((void**)&pt2,  g_t2);
    cudaGetSymbolAddress((void**)&pwt,  g_wt);

    const int GEMM_SMEM   = 4*GBUF*sizeof(float);              // 73728
    const int MSTATS_SMEM = (2*QTILE + 1024)*sizeof(float);    // 73728
    cudaFuncSetAttribute(gemm_mma,   cudaFuncAttributeMaxDynamicSharedMemorySize, GEMM_SMEM);
    cudaFuncSetAttribute(mstats_mma, cudaFuncAttributeMaxDynamicSharedMemorySize, MSTATS_SMEM);

    // transpose all weights: per layer [Wq,Wk,Wv,Wo,W1,W2]
    dim3 tgrid(16, 16), tblk(32, 8);
    for (int lay = 0; lay < NLL; lay++) {
        const float* srcs[6] = {
            Wq + (size_t)lay*DD*DD, Wk + (size_t)lay*DD*DD, Wv + (size_t)lay*DD*DD,
            Wo + (size_t)lay*DD*DD, W1 + (size_t)lay*DD*DD, W2 + (size_t)lay*DD*DD };
        for (int j = 0; j < 6; j++)
            transpose_kernel<<<tgrid, tblk>>>(srcs[j], pwt + (size_t)(lay*6 + j)*DD*DD);
    }

    embed_kernel<<<dim3(BL, DD/256), 256>>>(x, emb_w, emb_b);

    dim3 ggrid(DD/128, BL/128);       // (4, 64)

    for (int lay = 0; lay < NLL; lay++) {
        float* tWq = pwt + (size_t)(lay*6 + 0)*DD*DD;
        float* tWk = pwt + (size_t)(lay*6 + 1)*DD*DD;
        float* tWv = pwt + (size_t)(lay*6 + 2)*DD*DD;
        float* tWo = pwt + (size_t)(lay*6 + 3)*DD*DD;
        float* tW1 = pwt + (size_t)(lay*6 + 4)*DD*DD;
        float* tW2 = pwt + (size_t)(lay*6 + 5)*DD*DD;

        gemm_mma<<<ggrid, 256, GEMM_SMEM>>>(ph, tWq, bq + lay*DD, pq, 0);
        gemm_mma<<<ggrid, 256, GEMM_SMEM>>>(ph, tWk, bk + lay*DD, pk, 0);
        gemm_mma<<<ggrid, 256, GEMM_SMEM>>>(ph, tWv, bv + lay*DD, pv, 0);

        mstats_mma<<<dim3(LL/128, BB*HH), 256, MSTATS_SMEM>>>();
        topk_kernel<<<BB*HH, 256>>>();

        vmean_zero_kernel<<<BB*DD/256, 256>>>();
        vmean_part_kernel<<<dim3(DD/256, LL/128, BB), 256>>>();
        ctx_fill_kernel<<<dim3(BL, DD/256), 256>>>();
        attn_kernel<<<dim3(UU, BB*HH), 256>>>();

        gemm_mma<<<ggrid, 256, GEMM_SMEM>>>(pctx, tWo, bo + lay*DD, pt1, 0);
        lnres_kernel<<<BL, 256>>>(pt1, ln1_g + lay*DD, ln1_b + lay*DD);

        gemm_mma<<<ggrid, 256, GEMM_SMEM>>>(ph, tW1, b1 + lay*DD, pt1, 1);
        gemm_mma<<<ggrid, 256, GEMM_SMEM>>>(pt1, tW2, b2 + lay*DD, pt2, 0);
        lnres_kernel<<<BL, 256>>>(pt2, ln2_g + lay*DD, ln2_b + lay*DD);
    }

    proj_kernel<<<BB*PP, 256>>>(proj_w, proj_b, out);
}

// round 4
// speedup vs baseline: 2.8019x; 1.2508x over previous
#include <cuda_runtime.h>
#include <math.h>
#include <cstdint>

// Problem constants
#define BB   4
#define LL   2048
#define EE   7
#define DD   512
#define HH   8
#define DHH  64
#define PP   720
#define NLL  2
#define UU   40
#define BL   (BB*LL)          // 8192 rows
#define SCALE 0.125f          // 1/sqrt(64)
#define ASPLIT 8
#define ATILES (16/ASPLIT)    // key tiles of 128 per split block

// ---------------- scratch (device globals; no allocation allowed) ----------
__device__ float g_h[BL*DD];
__device__ float g_q[BL*DD];
__device__ float g_k[BL*DD];
__device__ float g_v[BL*DD];
__device__ float g_ctx[BL*DD];
__device__ float g_t1[BL*DD];
__device__ float g_t2[BL*DD];
__device__ float g_M[BB*HH*LL];
__device__ float g_vmean[BB*DD];
__device__ int   g_topk[BB*HH*UU];
__device__ float g_wt[12*DD*DD];            // transposed weights, [n][k]
__device__ float g_pacc[32*ASPLIT*UU*DHH];  // split-KV partial outputs
__device__ float g_pm[32*ASPLIT*UU];
__device__ float g_pl[32*ASPLIT*UU];
__device__ float g_pvs[32*ASPLIT*DHH];      // partial V column sums

// ---------------- tf32 helpers ---------------------------------------------
__device__ __forceinline__ float totf32(float x) {
    uint32_t r;
    asm("cvt.rna.tf32.f32 %0, %1;" : "=r"(r) : "f"(x));
    return __uint_as_float(r);
}
__device__ __forceinline__ void mma_tf32(float c[4], const uint32_t a[4], const uint32_t b[2]) {
    asm volatile("mma.sync.aligned.m16n8k8.row.col.f32.tf32.tf32.f32 "
        "{%0,%1,%2,%3}, {%4,%5,%6,%7}, {%8,%9}, {%0,%1,%2,%3};"
        : "+f"(c[0]), "+f"(c[1]), "+f"(c[2]), "+f"(c[3])
        : "r"(a[0]), "r"(a[1]), "r"(a[2]), "r"(a[3]), "r"(b[0]), "r"(b[1]));
}

// ---------------- batched weight transpose: Wt[n][k] = W[k][n] -------------
__global__ void transpose_all(const float* __restrict__ Wq, const float* __restrict__ Wk,
                              const float* __restrict__ Wv, const float* __restrict__ Wo,
                              const float* __restrict__ W1, const float* __restrict__ W2) {
    __shared__ float tile[32][33];
    int z = blockIdx.z;
    int lay = z / 6, j = z % 6;
    const float* W = (j==0?Wq : j==1?Wk : j==2?Wv : j==3?Wo : j==4?W1 : W2)
                     + (size_t)lay*DD*DD;
    float* Wt = g_wt + (size_t)z*DD*DD;
    int x0 = blockIdx.x*32, y0 = blockIdx.y*32;
    int tx = threadIdx.x, ty = threadIdx.y;   // (32,8)
#pragma unroll
    for (int jj = 0; jj < 32; jj += 8)
        tile[ty+jj][tx] = W[(size_t)(y0+ty+jj)*DD + x0+tx];
    __syncthreads();
#pragma unroll
    for (int jj = 0; jj < 32; jj += 8)
        Wt[(size_t)(x0+ty+jj)*DD + y0+tx] = tile[tx][ty+jj];
}

// ---------------- embedding: h = x @ emb_w + emb_b -------------------------
__global__ void embed_kernel(const float* __restrict__ x,
                             const float* __restrict__ w,
                             const float* __restrict__ b) {
    int row = blockIdx.x;
    int d   = blockIdx.y * 256 + threadIdx.x;
    __shared__ float xs[EE];
    if (threadIdx.x < EE) xs[threadIdx.x] = x[row*EE + threadIdx.x];
    __syncthreads();
    float acc = b[d];
#pragma unroll
    for (int e = 0; e < EE; e++) acc += xs[e] * w[e*DD + d];
    g_h[(size_t)row*DD + d] = acc;
}

// =============== tf32 mma.sync GEMM body ===================================
#define GPAD 36
#define GBUF (128*GPAD)
__device__ __forceinline__ void gemm_body(const float* __restrict__ A,
                                          const float* __restrict__ Bt,
                                          const float* __restrict__ bias,
                                          float* __restrict__ C, int relu,
                                          float* sm) {
    float* As = sm;                 // [2][GBUF]
    float* Bs = sm + 2*GBUF;        // [2][GBUF]

    int t = threadIdx.x, w = t >> 5, l = t & 31;
    int g = l >> 2, tig = l & 3;
    int wm = w >> 2, wn = w & 3;
    int m0 = blockIdx.y * 128, n0 = blockIdx.x * 128;

    const float* Ab = A  + (size_t)m0 * DD;
    const float* Bb = Bt + (size_t)n0 * DD;

    float c[4][4][4];
#pragma unroll
    for (int i = 0; i < 4; i++)
#pragma unroll
        for (int j = 0; j < 4; j++)
#pragma unroll
            for (int r = 0; r < 4; r++) c[i][j][r] = 0.f;

    int lrow = t >> 3;
    int lc4  = (t & 7) * 4;

    float4 aL[4], bL[4];
#pragma unroll
    for (int r = 0; r < 4; r++) {
        int row = r*32 + lrow;
        aL[r] = *(const float4*)(Ab + (size_t)row*DD + lc4);
        bL[r] = *(const float4*)(Bb + (size_t)row*DD + lc4);
    }
#pragma unroll
    for (int r = 0; r < 4; r++) {
        int row = r*32 + lrow;
        As[row*GPAD + lc4+0] = totf32(aL[r].x); As[row*GPAD + lc4+1] = totf32(aL[r].y);
        As[row*GPAD + lc4+2] = totf32(aL[r].z); As[row*GPAD + lc4+3] = totf32(aL[r].w);
        Bs[row*GPAD + lc4+0] = totf32(bL[r].x); Bs[row*GPAD + lc4+1] = totf32(bL[r].y);
        Bs[row*GPAD + lc4+2] = totf32(bL[r].z); Bs[row*GPAD + lc4+3] = totf32(bL[r].w);
    }
    __syncthreads();

    for (int chunk = 0; chunk < 16; chunk++) {
        int p = chunk & 1;
        if (chunk < 15) {
            int k0 = (chunk + 1) * 32;
#pragma unroll
            for (int r = 0; r < 4; r++) {
                int row = r*32 + lrow;
                aL[r] = *(const float4*)(Ab + (size_t)row*DD + k0 + lc4);
                bL[r] = *(const float4*)(Bb + (size_t)row*DD + k0 + lc4);
            }
        }
        const float* Ap = As + p*GBUF;
        const float* Bp = Bs + p*GBUF;
#pragma unroll
        for (int kk = 0; kk < 4; kk++) {
            int kb = kk * 8;
            uint32_t af[4][4];
#pragma unroll
            for (int mt = 0; mt < 4; mt++) {
                int base = (wm*64 + mt*16 + g)*GPAD + kb + tig;
                af[mt][0] = __float_as_uint(Ap[base]);
                af[mt][1] = __float_as_uint(Ap[base + 8*GPAD]);
                af[mt][2] = __float_as_uint(Ap[base + 4]);
                af[mt][3] = __float_as_uint(Ap[base + 8*GPAD + 4]);
            }
            uint32_t bf[4][2];
#pragma unroll
            for (int nt = 0; nt < 4; nt++) {
                int base = (wn*32 + nt*8 + g)*GPAD + kb + tig;
                bf[nt][0] = __float_as_uint(Bp[base]);
                bf[nt][1] = __float_as_uint(Bp[base + 4]);
            }
#pragma unroll
            for (int mt = 0; mt < 4; mt++)
#pragma unroll
                for (int nt = 0; nt < 4; nt++)
                    mma_tf32(c[mt][nt], af[mt], bf[nt]);
        }
        __syncthreads();
        if (chunk < 15) {
            float* Ad = As + (p^1)*GBUF;
            float* Bd = Bs + (p^1)*GBUF;
#pragma unroll
            for (int r = 0; r < 4; r++) {
                int row = r*32 + lrow;
                Ad[row*GPAD + lc4+0] = totf32(aL[r].x); Ad[row*GPAD + lc4+1] = totf32(aL[r].y);
                Ad[row*GPAD + lc4+2] = totf32(aL[r].z); Ad[row*GPAD + lc4+3] = totf32(aL[r].w);
                Bd[row*GPAD + lc4+0] = totf32(bL[r].x); Bd[row*GPAD + lc4+1] = totf32(bL[r].y);
                Bd[row*GPAD + lc4+2] = totf32(bL[r].z); Bd[row*GPAD + lc4+3] = totf32(bL[r].w);
            }
            __syncthreads();
        }
    }

#pragma unroll
    for (int mt = 0; mt < 4; mt++) {
        int row = m0 + wm*64 + mt*16 + g;
#pragma unroll
        for (int nt = 0; nt < 4; nt++) {
            int col = n0 + wn*32 + nt*8 + 2*tig;
            float b0 = bias[col], b1 = bias[col+1];
            float2 v0 = make_float2(c[mt][nt][0] + b0, c[mt][nt][1] + b1);
            float2 v1 = make_float2(c[mt][nt][2] + b0, c[mt][nt][3] + b1);
            if (relu) {
                v0.x = fmaxf(v0.x, 0.f); v0.y = fmaxf(v0.y, 0.f);
                v1.x = fmaxf(v1.x, 0.f); v1.y = fmaxf(v1.y, 0.f);
            }
            *(float2*)(C + (size_t)row*DD + col)     = v0;
            *(float2*)(C + (size_t)(row+8)*DD + col) = v1;
        }
    }
}

__global__ void __launch_bounds__(256) gemm_mma(const float* __restrict__ A,
                                                const float* __restrict__ Bt,
                                                const float* __restrict__ bias,
                                                float* __restrict__ C, int relu) {
    extern __shared__ float sm[];
    gemm_body(A, Bt, bias, C, relu, sm);
}

// batched QKV: z selects weight (g_wt slots lay*6+z), bias, output
__global__ void __launch_bounds__(256) gemm_qkv(int lay,
                                                const float* __restrict__ bq,
                                                const float* __restrict__ bk,
                                                const float* __restrict__ bv) {
    extern __shared__ float sm[];
    int z = blockIdx.z;
    const float* Bt = g_wt + (size_t)(lay*6 + z)*DD*DD;
    const float* bias = (z==0) ? bq : (z==1) ? bk : bv;
    float* C = (z==0) ? g_q : (z==1) ? g_k : g_v;
    gemm_body(g_h, Bt, bias, C, 0, sm);
}

// ========= tf32 mma.sync score stats: M = SCALE*(max - mean) ===============
#define QPAD 68
#define QTILE (128*QPAD)
__global__ void __launch_bounds__(256) mstats_mma() {
    extern __shared__ float sm[];
    float* Qs   = sm;               // [128][QPAD]
    float* Ks   = sm + QTILE;       // [128][QPAD]
    float* redm = sm + 2*QTILE;     // [4][128]
    float* reds = sm + 2*QTILE + 512;

    int t = threadIdx.x, w = t >> 5, l = t & 31;
    int g = l >> 2, tig = l & 3;
    int wm = w >> 2, wn = w & 3;
    int bh = blockIdx.y, b = bh >> 3, h = bh & 7;
    int q0 = blockIdx.x * 128;

    const float* qb = g_q + (size_t)b*LL*DD + h*DHH;
    const float* kb = g_k + (size_t)b*LL*DD + h*DHH;

    int lrow = t >> 4;
    int lc4  = (t & 15) * 4;

#pragma unroll
    for (int r = 0; r < 8; r++) {
        int row = r*16 + lrow;
        float4 v = *(const float4*)(qb + (size_t)(q0 + row)*DD + lc4);
        Qs[row*QPAD + lc4+0] = totf32(v.x); Qs[row*QPAD + lc4+1] = totf32(v.y);
        Qs[row*QPAD + lc4+2] = totf32(v.z); Qs[row*QPAD + lc4+3] = totf32(v.w);
    }

    float mx[8], sum[8];
#pragma unroll
    for (int s = 0; s < 8; s++) { mx[s] = -INFINITY; sum[s] = 0.f; }

    for (int ntile = 0; ntile < 16; ntile++) {
        int n0 = ntile * 128;
#pragma unroll
        for (int r = 0; r < 8; r++) {
            int row = r*16 + lrow;
            float4 v = *(const float4*)(kb + (size_t)(n0 + row)*DD + lc4);
            Ks[row*QPAD + lc4+0] = totf32(v.x); Ks[row*QPAD + lc4+1] = totf32(v.y);
            Ks[row*QPAD + lc4+2] = totf32(v.z); Ks[row*QPAD + lc4+3] = totf32(v.w);
        }
        __syncthreads();

        float c[4][4][4];
#pragma unroll
        for (int i = 0; i < 4; i++)
#pragma unroll
            for (int j = 0; j < 4; j++)
#pragma unroll
                for (int r = 0; r < 4; r++) c[i][j][r] = 0.f;

#pragma unroll
        for (int kk = 0; kk < 8; kk++) {
            int kbs = kk * 8;
            uint32_t af[4][4];
#pragma unroll
            for (int mt = 0; mt < 4; mt++) {
                int base = (wm*64 + mt*16 + g)*QPAD + kbs + tig;
                af[mt][0] = __float_as_uint(Qs[base]);
                af[mt][1] = __float_as_uint(Qs[base + 8*QPAD]);
                af[mt][2] = __float_as_uint(Qs[base + 4]);
                af[mt][3] = __float_as_uint(Qs[base + 8*QPAD + 4]);
            }
            uint32_t bf[4][2];
#pragma unroll
            for (int nt = 0; nt < 4; nt++) {
                int base = (wn*32 + nt*8 + g)*QPAD + kbs + tig;
                bf[nt][0] = __float_as_uint(Ks[base]);
                bf[nt][1] = __float_as_uint(Ks[base + 4]);
            }
#pragma unroll
            for (int mt = 0; mt < 4; mt++)
#pragma unroll
                for (int nt = 0; nt < 4; nt++)
                    mma_tf32(c[mt][nt], af[mt], bf[nt]);
        }

#pragma unroll
        for (int mt = 0; mt < 4; mt++)
#pragma unroll
            for (int nt = 0; nt < 4; nt++) {
                mx[mt*2+0]  = fmaxf(mx[mt*2+0], fmaxf(c[mt][nt][0], c[mt][nt][1]));
                sum[mt*2+0] += c[mt][nt][0] + c[mt][nt][1];
                mx[mt*2+1]  = fmaxf(mx[mt*2+1], fmaxf(c[mt][nt][2], c[mt][nt][3]));
                sum[mt*2+1] += c[mt][nt][2] + c[mt][nt][3];
            }
        __syncthreads();
    }

#pragma unroll
    for (int s = 0; s < 8; s++) {
        mx[s]  = fmaxf(mx[s],  __shfl_xor_sync(0xffffffff, mx[s], 1));
        mx[s]  = fmaxf(mx[s],  __shfl_xor_sync(0xffffffff, mx[s], 2));
        sum[s] += __shfl_xor_sync(0xffffffff, sum[s], 1);
        sum[s] += __shfl_xor_sync(0xffffffff, sum[s], 2);
    }
    if (tig == 0) {
#pragma unroll
        for (int mt = 0; mt < 4; mt++)
#pragma unroll
            for (int hi = 0; hi < 2; hi++) {
                int row = wm*64 + mt*16 + g + hi*8;
                redm[wn*128 + row] = mx[mt*2+hi];
                reds[wn*128 + row] = sum[mt*2+hi];
            }
    }
    __syncthreads();
    if (t < 128) {
        float m = redm[t], s = reds[t];
#pragma unroll
        for (int x = 1; x < 4; x++) {
            m = fmaxf(m, redm[x*128 + t]);
            s += reds[x*128 + t];
        }
        g_M[(size_t)bh*LL + q0 + t] = SCALE * (m - s * (1.f/LL));
    }
}

// ---------------- top-U selection per (b,h), JAX tie-break (lower idx) -----
__global__ void topk_kernel() {
    __shared__ float vals[LL];
    __shared__ float rv[256];
    __shared__ int   ri[256];
    int t  = threadIdx.x;
    int bh = blockIdx.x;
    for (int i = t; i < LL; i += 256) vals[i] = g_M[(size_t)bh*LL + i];
    __syncthreads();
    for (int u = 0; u < UU; u++) {
        float bv = -INFINITY; int bi = 0x7fffffff;
        for (int i = t; i < LL; i += 256) {
            float v = vals[i];
            if (v > bv) { bv = v; bi = i; }
        }
        rv[t] = bv; ri[t] = bi;
        __syncthreads();
        for (int s = 128; s > 0; s >>= 1) {
            if (t < s) {
                float ov = rv[t+s]; int oi = ri[t+s];
                if (ov > rv[t] || (ov == rv[t] && oi < ri[t])) { rv[t] = ov; ri[t] = oi; }
            }
            __syncthreads();
        }
        if (t == 0) { g_topk[bh*UU + u] = ri[0]; vals[ri[0]] = -INFINITY; }
        __syncthreads();
    }
}

// =============== fused split-KV sparse attention ===========================
// grid (ASPLIT, 32). Block: 40 selected Q rows resident; streams ATILES
// K/V tiles of 128 with online softmax; also accumulates V column sums.
// SMEM floats: Qs[40][68] Ks[128][68] Vs[128][68] S[40][132] m/al/l[40]
#define ATT_SMEM_FLOATS (2720 + 8704 + 8704 + 5280 + 120)
__global__ void __launch_bounds__(256) attn_part() {
    extern __shared__ float sm[];
    float* Qs = sm;
    float* Ks = sm + 2720;
    float* Vs = sm + 11424;
    float* S  = sm + 20128;
    float* Mv = sm + 25408;
    float* Al = sm + 25448;
    float* Lv = sm + 25488;

    int t = threadIdx.x;
    int split = blockIdx.x, bh = blockIdx.y;
    int b = bh >> 3, h = bh & 7;
    int w = t >> 5, l = t & 31;
    int j = t & 127, qs = t >> 7;    // score mapping (q same per warp)
    int d = t & 63,  qg = t >> 6;    // acc mapping

    // load the 40 selected Q rows
    for (int idx = t; idx < 640; idx += 256) {
        int u = idx >> 4, c4 = (idx & 15) * 4;
        int lq = g_topk[bh*UU + u];
        *(float4*)&Qs[u*68 + c4] =
            *(const float4*)&g_q[((size_t)(b*LL + lq))*DD + h*DHH + c4];
    }
    if (t < 40) { Mv[t] = -INFINITY; Lv[t] = 0.f; }

    float acc[10];
#pragma unroll
    for (int i = 0; i < 10; i++) acc[i] = 0.f;
    float vsum = 0.f;

    for (int tt = 0; tt < ATILES; tt++) {
        int n0 = (split*ATILES + tt) * 128;
        __syncthreads();            // Qs ready (1st) / Ks,Vs,S free (later)
#pragma unroll
        for (int r = 0; r < 8; r++) {
            int idx = r*256 + t;
            int row = idx >> 4, c4 = (idx & 15) * 4;
            size_t gofs = ((size_t)(b*LL + n0 + row))*DD + h*DHH + c4;
            *(float4*)&Ks[row*68 + c4] = *(const float4*)&g_k[gofs];
            *(float4*)&Vs[row*68 + c4] = *(const float4*)&g_v[gofs];
        }
        __syncthreads();

        if (t < 64)
            for (int jj = 0; jj < 128; jj++) vsum += Vs[jj*68 + t];

        // scores: thread handles fixed j, q = qs + 2i
        float s[20];
#pragma unroll
        for (int i = 0; i < 20; i++) s[i] = 0.f;
#pragma unroll
        for (int d4 = 0; d4 < 16; d4++) {
            float4 kv = *(float4*)&Ks[j*68 + d4*4];
#pragma unroll
            for (int i = 0; i < 20; i++) {
                float4 qv = *(float4*)&Qs[(qs + 2*i)*68 + d4*4];
                s[i] += qv.x*kv.x + qv.y*kv.y + qv.z*kv.z + qv.w*kv.w;
            }
        }
#pragma unroll
        for (int i = 0; i < 20; i++) S[(qs + 2*i)*132 + j] = s[i] * SCALE;
        __syncthreads();

        // per-q tile max (warp w owns q = w*5 .. w*5+4)
#pragma unroll
        for (int r = 0; r < 5; r++) {
            int q = w*5 + r;
            float mx = fmaxf(fmaxf(S[q*132 + l], S[q*132 + l + 32]),
                             fmaxf(S[q*132 + l + 64], S[q*132 + l + 96]));
#pragma unroll
            for (int o = 16; o; o >>= 1) mx = fmaxf(mx, __shfl_xor_sync(~0u, mx, o));
            if (l == 0) {
                float mn = fmaxf(Mv[q], mx);
                Al[q] = __expf(Mv[q] - mn);
                Mv[q] = mn;
            }
        }
        __syncthreads();

        // exponentiate in place
#pragma unroll
        for (int i = 0; i < 20; i++) {
            int q = qs + 2*i;
            S[q*132 + j] = __expf(S[q*132 + j] - Mv[q]);
        }
        __syncthreads();

        // l update (warp-owned q) + accumulator update (all threads)
#pragma unroll
        for (int r = 0; r < 5; r++) {
            int q = w*5 + r;
            float sme = S[q*132 + l] + S[q*132 + l + 32]
                      + S[q*132 + l + 64] + S[q*132 + l + 96];
#pragma unroll
            for (int o = 16; o; o >>= 1) sme += __shfl_xor_sync(~0u, sme, o);
            if (l == 0) Lv[q] = Lv[q]*Al[q] + sme;
        }
#pragma unroll
        for (int i = 0; i < 10; i++) {
            int q = qg + 4*i;
            float a = acc[i] * Al[q];
            for (int jj = 0; jj < 128; jj++)
                a += S[q*132 + jj] * Vs[jj*68 + d];
            acc[i] = a;
        }
    }
    __syncthreads();

    int base = bh*ASPLIT + split;
#pragma unroll
    for (int i = 0; i < 10; i++) {
        int q = qg + 4*i;
        g_pacc[((size_t)base*UU + q)*DHH + d] = acc[i];
    }
    if (t < 40) { g_pm[base*UU + t] = Mv[t]; g_pl[base*UU + t] = Lv[t]; }
    if (t < 64) g_pvs[base*DHH + t] = vsum;
}

// combine V-mean partials -> g_vmean
__global__ void vmean_combine() {
    int bh = blockIdx.x, t = threadIdx.x;     // <<<32, 64>>>
    int b = bh >> 3, h = bh & 7;
    float s = 0.f;
#pragma unroll
    for (int sp = 0; sp < ASPLIT; sp++) s += g_pvs[(bh*ASPLIT + sp)*DHH + t];
    g_vmean[b*DD + h*DHH + t] = s;
}

__global__ void ctx_fill_kernel() {
    int row = blockIdx.x;
    int d   = blockIdx.y*256 + threadIdx.x;
    int b   = row >> 11;
    g_ctx[(size_t)row*DD + d] = g_vmean[b*DD + d] * (1.f/LL);
}

// combine split-KV partials -> g_ctx rows for selected queries
__global__ void attn_combine() {
    int t = threadIdx.x, bh = blockIdx.x;     // <<<32, 256>>>
    int b = bh >> 3, h = bh & 7;
    int d = t & 63, qg = t >> 6;
#pragma unroll
    for (int i = 0; i < 10; i++) {
        int q = qg + 4*i;
        float ms[ASPLIT], M = -INFINITY;
#pragma unroll
        for (int s = 0; s < ASPLIT; s++) {
            ms[s] = g_pm[(bh*ASPLIT + s)*UU + q];
            M = fmaxf(M, ms[s]);
        }
        float L = 0.f, o = 0.f;
#pragma unroll
        for (int s = 0; s < ASPLIT; s++) {
            float wv = __expf(ms[s] - M);
            L += g_pl[(bh*ASPLIT + s)*UU + q] * wv;
            o += g_pacc[((size_t)(bh*ASPLIT + s)*UU + q)*DHH + d] * wv;
        }
        int lq = g_topk[bh*UU + q];
        g_ctx[((size_t)(b*LL + lq))*DD + h*DHH + d] = o / L;
    }
}

// ---------------- residual + LayerNorm -> g_h ------------------------------
__global__ void lnres_kernel(const float* __restrict__ delta,
                             const float* __restrict__ gam,
                             const float* __restrict__ bet) {
    int row = blockIdx.x;
    int t   = threadIdx.x;
    __shared__ float red[256];
    float v0 = g_h[(size_t)row*DD + t]       + delta[(size_t)row*DD + t];
    float v1 = g_h[(size_t)row*DD + t + 256] + delta[(size_t)row*DD + t + 256];
    red[t] = v0 + v1; __syncthreads();
    for (int s = 128; s > 0; s >>= 1) { if (t < s) red[t] += red[t+s]; __syncthreads(); }
    float mean = red[0] * (1.f/DD);
    __syncthreads();
    float d0 = v0 - mean, d1 = v1 - mean;
    red[t] = d0*d0 + d1*d1; __syncthreads();
    for (int s = 128; s > 0; s >>= 1) { if (t < s) red[t] += red[t+s]; __syncthreads(); }
    float inv = rsqrtf(red[0]*(1.f/DD) + 1e-5f);
    g_h[(size_t)row*DD + t]       = d0*inv*gam[t]     + bet[t];
    g_h[(size_t)row*DD + t + 256] = d1*inv*gam[t+256] + bet[t+256];
}

// ---------------- final projection -----------------------------------------
__global__ void proj_kernel(const float* __restrict__ w,
                            const float* __restrict__ b,
                            float* __restrict__ out) {
    int t  = threadIdx.x;
    int bp = blockIdx.x;
    int bb = bp / PP, p = bp % PP;
    int row = bb*LL + (LL - PP) + p;
    float acc[EE];
#pragma unroll
    for (int e = 0; e < EE; e++) acc[e] = 0.f;
    for (int d = t; d < DD; d += 256) {
        float hv = g_h[(size_t)row*DD + d];
#pragma unroll
        for (int e = 0; e < EE; e++) acc[e] += hv * w[d*EE + e];
    }
    __shared__ float red[256];
#pragma unroll
    for (int e = 0; e < EE; e++) {
        red[t] = acc[e]; __syncthreads();
        for (int s = 128; s > 0; s >>= 1) { if (t < s) red[t] += red[t+s]; __syncthreads(); }
        if (t == 0) out[bp*EE + e] = red[0] + b[e];
        __syncthreads();
    }
}

// ---------------- host orchestration ---------------------------------------
extern "C" void kernel_launch(void* const* d_in, const int* in_sizes, int n_in,
                              void* d_out, int out_size) {
    const float* x      = (const float*)d_in[0];
    const float* emb_w  = (const float*)d_in[1];
    const float* emb_b  = (const float*)d_in[2];
    const float* Wq     = (const float*)d_in[3];
    const float* bq     = (const float*)d_in[4];
    const float* Wk     = (const float*)d_in[5];
    const float* bk     = (const float*)d_in[6];
    const float* Wv     = (const float*)d_in[7];
    const float* bv     = (const float*)d_in[8];
    const float* Wo     = (const float*)d_in[9];
    const float* bo     = (const float*)d_in[10];
    const float* W1     = (const float*)d_in[11];
    const float* b1     = (const float*)d_in[12];
    const float* W2     = (const float*)d_in[13];
    const float* b2     = (const float*)d_in[14];
    const float* ln1_g  = (const float*)d_in[15];
    const float* ln1_b  = (const float*)d_in[16];
    const float* ln2_g  = (const float*)d_in[17];
    const float* ln2_b  = (const float*)d_in[18];
    const float* proj_w = (const float*)d_in[19];
    const float* proj_b = (const float*)d_in[20];
    float* out = (float*)d_out;

    float *ph, *pctx, *pt1, *pt2, *pwt;
    cudaGetSymbolAddress((void**)&ph,   g_h);
    cudaGetSymbolAddress((void**)&pctx, g_ctx);
    cudaGetSymbolAddress((void**)&pt1,  g_t1);
    cudaGetSymbolAddress((void**)&pt2,  g_t2);
    cudaGetSymbolAddress((void**)&pwt,  g_wt);

    const int GEMM_SMEM   = 4*GBUF*sizeof(float);              // 73728
    const int MSTATS_SMEM = (2*QTILE + 1024)*sizeof(float);    // 73728
    const int ATT_SMEM    = ATT_SMEM_FLOATS*sizeof(float);     // 102112
    cudaFuncSetAttribute(gemm_mma,   cudaFuncAttributeMaxDynamicSharedMemorySize, GEMM_SMEM);
    cudaFuncSetAttribute(gemm_qkv,   cudaFuncAttributeMaxDynamicSharedMemorySize, GEMM_SMEM);
    cudaFuncSetAttribute(mstats_mma, cudaFuncAttributeMaxDynamicSharedMemorySize, MSTATS_SMEM);
    cudaFuncSetAttribute(attn_part,  cudaFuncAttributeMaxDynamicSharedMemorySize, ATT_SMEM);

    transpose_all<<<dim3(16, 16, 12), dim3(32, 8)>>>(Wq, Wk, Wv, Wo, W1, W2);
    embed_kernel<<<dim3(BL, DD/256), 256>>>(x, emb_w, emb_b);

    dim3 ggrid(DD/128, BL/128);       // (4, 64)

    for (int lay = 0; lay < NLL; lay++) {
        float* tWo = pwt + (size_t)(lay*6 + 3)*DD*DD;
        float* tW1 = pwt + (size_t)(lay*6 + 4)*DD*DD;
        float* tW2 = pwt + (size_t)(lay*6 + 5)*DD*DD;

        gemm_qkv<<<dim3(DD/128, BL/128, 3), 256, GEMM_SMEM>>>(
            lay, bq + lay*DD, bk + lay*DD, bv + lay*DD);

        mstats_mma<<<dim3(LL/128, BB*HH), 256, MSTATS_SMEM>>>();
        topk_kernel<<<BB*HH, 256>>>();

        attn_part<<<dim3(ASPLIT, BB*HH), 256, ATT_SMEM>>>();
        vmean_combine<<<BB*HH, 64>>>();
        ctx_fill_kernel<<<dim3(BL, DD/256), 256>>>();
        attn_combine<<<BB*HH, 256>>>();

        gemm_mma<<<ggrid, 256, GEMM_SMEM>>>(pctx, tWo, bo + lay*DD, pt1, 0);
        lnres_kernel<<<BL, 256>>>(pt1, ln1_g + lay*DD, ln1_b + lay*DD);

        gemm_mma<<<ggrid, 256, GEMM_SMEM>>>(ph, tW1, b1 + lay*DD, pt1, 1);
        gemm_mma<<<ggrid, 256, GEMM_SMEM>>>(pt1, tW2, b2 + lay*DD, pt2, 0);
        lnres_kernel<<<BL, 256>>>(pt2, ln2_g + lay*DD, ln2_b + lay*DD);
    }

    proj_kernel<<<BB*PP, 256>>>(proj_w, proj_b, out);
}

// round 5
// speedup vs baseline: 3.2220x; 1.1500x over previous
#include <cuda_runtime.h>
#include <math.h>
#include <cstdint>

// Problem constants
#define BB   4
#define LL   2048
#define EE   7
#define DD   512
#define HH   8
#define DHH  64
#define PP   720
#define NLL  2
#define UU   40
#define BL   (BB*LL)          // 8192 rows
#define SCALE 0.125f          // 1/sqrt(64)
#define ASPLIT 8
#define ATILES (16/ASPLIT)    // key tiles of 128 per split block

// ---------------- scratch (device globals; no allocation allowed) ----------
__device__ float g_h[BL*DD];
__device__ float g_q[BL*DD];
__device__ float g_k[BL*DD];
__device__ float g_v[BL*DD];
__device__ float g_ctx[BL*DD];
__device__ float g_t1[BL*DD];
__device__ float g_t2[BL*DD];
__device__ float g_M[BB*HH*LL];
__device__ float g_vmean[BB*DD];
__device__ int   g_topk[BB*HH*UU];
__device__ float g_wt[12*DD*DD];            // transposed weights, [n][k], tf32-rounded
__device__ float g_pacc[32*ASPLIT*UU*DHH];  // split-KV partial outputs
__device__ float g_pm[32*ASPLIT*UU];
__device__ float g_pl[32*ASPLIT*UU];
__device__ float g_pvs[32*ASPLIT*DHH];      // partial V column sums

// ---------------- helpers ---------------------------------------------------
__device__ __forceinline__ float totf32(float x) {
    uint32_t r;
    asm("cvt.rna.tf32.f32 %0, %1;" : "=r"(r) : "f"(x));
    return __uint_as_float(r);
}
__device__ __forceinline__ void mma_tf32(float c[4], const uint32_t a[4], const uint32_t b[2]) {
    asm volatile("mma.sync.aligned.m16n8k8.row.col.f32.tf32.tf32.f32 "
        "{%0,%1,%2,%3}, {%4,%5,%6,%7}, {%8,%9}, {%0,%1,%2,%3};"
        : "+f"(c[0]), "+f"(c[1]), "+f"(c[2]), "+f"(c[3])
        : "r"(a[0]), "r"(a[1]), "r"(a[2]), "r"(a[3]), "r"(b[0]), "r"(b[1]));
}
__device__ __forceinline__ uint32_t smem_u32(const void* p) {
    uint32_t a;
    asm("{ .reg .u64 t; cvta.to.shared.u64 t, %1; cvt.u32.u64 %0, t; }" : "=r"(a) : "l"(p));
    return a;
}
__device__ __forceinline__ void cp_async16(uint32_t s, const void* g) {
    asm volatile("cp.async.cg.shared.global [%0], [%1], 16;" :: "r"(s), "l"(g));
}
#define CP_COMMIT() asm volatile("cp.async.commit_group;" ::: "memory")
#define CP_WAIT(n)  asm volatile("cp.async.wait_group %0;" :: "n"(n) : "memory")

// ---------------- batched weight transpose: Wt[n][k] = tf32(W[k][n]) -------
__global__ void transpose_all(const float* __restrict__ Wq, const float* __restrict__ Wk,
                              const float* __restrict__ Wv, const float* __restrict__ Wo,
                              const float* __restrict__ W1, const float* __restrict__ W2) {
    __shared__ float tile[32][33];
    int z = blockIdx.z;
    int lay = z / 6, j = z % 6;
    const float* W = (j==0?Wq : j==1?Wk : j==2?Wv : j==3?Wo : j==4?W1 : W2)
                     + (size_t)lay*DD*DD;
    float* Wt = g_wt + (size_t)z*DD*DD;
    int x0 = blockIdx.x*32, y0 = blockIdx.y*32;
    int tx = threadIdx.x, ty = threadIdx.y;   // (32,8)
#pragma unroll
    for (int jj = 0; jj < 32; jj += 8)
        tile[ty+jj][tx] = W[(size_t)(y0+ty+jj)*DD + x0+tx];
    __syncthreads();
#pragma unroll
    for (int jj = 0; jj < 32; jj += 8)
        Wt[(size_t)(x0+ty+jj)*DD + y0+tx] = totf32(tile[tx][ty+jj]);
}

// ---------------- embedding: h = x @ emb_w + emb_b -------------------------
__global__ void embed_kernel(const float* __restrict__ x,
                             const float* __restrict__ w,
                             const float* __restrict__ b) {
    int row = blockIdx.x;
    int d   = blockIdx.y * 256 + threadIdx.x;
    __shared__ float xs[EE];
    if (threadIdx.x < EE) xs[threadIdx.x] = x[row*EE + threadIdx.x];
    __syncthreads();
    float acc = b[d];
#pragma unroll
    for (int e = 0; e < EE; e++) acc += xs[e] * w[e*DD + d];
    g_h[(size_t)row*DD + d] = acc;
}

// =============== tf32 mma.sync GEMM (cp.async 3-stage) =====================
// A[8192,512] K-major (raw fp32, HW-truncated), Bt = tf32-rounded W^T [N,K].
// CTA 128x128, 8 warps (2m x 4n), K chunks of 32, 3-stage cp.async ring.
#define GPAD 36
#define GBUF (128*GPAD)
#define GSTAGE 3
__device__ __forceinline__ void gemm_body(const float* __restrict__ A,
                                          const float* __restrict__ Bt,
                                          const float* __restrict__ bias,
                                          float* __restrict__ C, int relu,
                                          float* sm) {
    int t = threadIdx.x, l = t & 31, w = t >> 5;
    int g = l >> 2, tig = l & 3;
    int wm = w >> 2, wn = w & 3;
    int m0 = blockIdx.y * 128, n0 = blockIdx.x * 128;

    const float* Ab = A  + (size_t)m0 * DD;
    const float* Bb = Bt + (size_t)n0 * DD;

    uint32_t sA = smem_u32(sm);
    uint32_t sB = sA + GSTAGE*GBUF*4;

    int irow = t >> 3;            // 0..31 base rows (4 per thread via +32r? no: 1024 copies)
    // per chunk: 1024 16B copies per matrix; thread does 4: idx = r*256+t
    int ic = (t & 7) * 4;         // float col
#define GEMM_ISSUE(chunk, stage) do {                                          \
        int _k0 = (chunk) * 32;                                                \
        uint32_t _oa = sA + (uint32_t)(stage)*GBUF*4;                          \
        uint32_t _ob = sB + (uint32_t)(stage)*GBUF*4;                          \
        _Pragma("unroll")                                                      \
        for (int _r = 0; _r < 4; _r++) {                                       \
            int _row = _r*32 + irow;                                           \
            uint32_t _so = (uint32_t)(_row*GPAD + ic)*4;                       \
            cp_async16(_oa + _so, Ab + (size_t)_row*DD + _k0 + ic);            \
            cp_async16(_ob + _so, Bb + (size_t)_row*DD + _k0 + ic);            \
        }                                                                      \
        CP_COMMIT();                                                           \
    } while (0)

    float c[4][4][4];
#pragma unroll
    for (int i = 0; i < 4; i++)
#pragma unroll
        for (int j = 0; j < 4; j++)
#pragma unroll
            for (int r = 0; r < 4; r++) c[i][j][r] = 0.f;

    GEMM_ISSUE(0, 0);
    GEMM_ISSUE(1, 1);

    for (int chunk = 0; chunk < 16; chunk++) {
        if (chunk < 15) { CP_WAIT(1); } else { CP_WAIT(0); }
        __syncthreads();
        if (chunk + 2 < 16) GEMM_ISSUE(chunk + 2, (chunk + 2) % GSTAGE);

        const float* Ap = sm + (chunk % GSTAGE)*GBUF;
        const float* Bp = sm + (GSTAGE + chunk % GSTAGE)*GBUF;
#pragma unroll
        for (int kk = 0; kk < 4; kk++) {
            int kb = kk * 8;
            uint32_t af[4][4];
#pragma unroll
            for (int mt = 0; mt < 4; mt++) {
                int base = (wm*64 + mt*16 + g)*GPAD + kb + tig;
                af[mt][0] = __float_as_uint(Ap[base]);
                af[mt][1] = __float_as_uint(Ap[base + 8*GPAD]);
                af[mt][2] = __float_as_uint(Ap[base + 4]);
                af[mt][3] = __float_as_uint(Ap[base + 8*GPAD + 4]);
            }
            uint32_t bf[4][2];
#pragma unroll
            for (int nt = 0; nt < 4; nt++) {
                int base = (wn*32 + nt*8 + g)*GPAD + kb + tig;
                bf[nt][0] = __float_as_uint(Bp[base]);
                bf[nt][1] = __float_as_uint(Bp[base + 4]);
            }
#pragma unroll
            for (int mt = 0; mt < 4; mt++)
#pragma unroll
                for (int nt = 0; nt < 4; nt++)
                    mma_tf32(c[mt][nt], af[mt], bf[nt]);
        }
        __syncthreads();
    }

#pragma unroll
    for (int mt = 0; mt < 4; mt++) {
        int row = m0 + wm*64 + mt*16 + g;
#pragma unroll
        for (int nt = 0; nt < 4; nt++) {
            int col = n0 + wn*32 + nt*8 + 2*tig;
            float b0 = bias[col], b1 = bias[col+1];
            float2 v0 = make_float2(c[mt][nt][0] + b0, c[mt][nt][1] + b1);
            float2 v1 = make_float2(c[mt][nt][2] + b0, c[mt][nt][3] + b1);
            if (relu) {
                v0.x = fmaxf(v0.x, 0.f); v0.y = fmaxf(v0.y, 0.f);
                v1.x = fmaxf(v1.x, 0.f); v1.y = fmaxf(v1.y, 0.f);
            }
            *(float2*)(C + (size_t)row*DD + col)     = v0;
            *(float2*)(C + (size_t)(row+8)*DD + col) = v1;
        }
    }
#undef GEMM_ISSUE
}

__global__ void __launch_bounds__(256) gemm_mma(const float* __restrict__ A,
                                                const float* __restrict__ Bt,
                                                const float* __restrict__ bias,
                                                float* __restrict__ C, int relu) {
    extern __shared__ float sm[];
    gemm_body(A, Bt, bias, C, relu, sm);
}

__global__ void __launch_bounds__(256) gemm_qkv(int lay,
                                                const float* __restrict__ bq,
                                                const float* __restrict__ bk,
                                                const float* __restrict__ bv) {
    extern __shared__ float sm[];
    int z = blockIdx.z;
    const float* Bt = g_wt + (size_t)(lay*6 + z)*DD*DD;
    const float* bias = (z==0) ? bq : (z==1) ? bk : bv;
    float* C = (z==0) ? g_q : (z==1) ? g_k : g_v;
    gemm_body(g_h, Bt, bias, C, 0, sm);
}

// ========= score stats: M = SCALE*(max - mean), cp.async double-buffer =====
#define QPAD 68
#define QTILE (128*QPAD)
__global__ void __launch_bounds__(256) mstats_mma() {
    extern __shared__ float sm[];
    float* Qs   = sm;                     // [128][QPAD]
    float* redm = sm + 3*QTILE;           // [4][128]
    float* reds = sm + 3*QTILE + 512;

    int t = threadIdx.x, w = t >> 5, l = t & 31;
    int g = l >> 2, tig = l & 3;
    int wm = w >> 2, wn = w & 3;
    int bh = blockIdx.y, b = bh >> 3, h = bh & 7;
    int q0 = blockIdx.x * 128;

    const float* qb = g_q + (size_t)b*LL*DD + h*DHH;
    const float* kb = g_k + (size_t)b*LL*DD + h*DHH;

    uint32_t sK = smem_u32(sm) + QTILE*4;     // 2 stages of [128][QPAD]

    int lrow8 = t >> 4;           // 0..15
    int lc4   = (t & 15) * 4;

#define MST_ISSUE(nt, stage) do {                                              \
        int _n0 = (nt) * 128;                                                  \
        uint32_t _ok = sK + (uint32_t)(stage)*QTILE*4;                         \
        _Pragma("unroll")                                                      \
        for (int _r = 0; _r < 8; _r++) {                                       \
            int _row = _r*16 + lrow8;                                          \
            cp_async16(_ok + (uint32_t)(_row*QPAD + lc4)*4,                    \
                       kb + (size_t)(_n0 + _row)*DD + lc4);                    \
        }                                                                      \
        CP_COMMIT();                                                           \
    } while (0)

    // Q tile [128][64] resident, raw fp32
#pragma unroll
    for (int r = 0; r < 8; r++) {
        int row = r*16 + lrow8;
        *(float4*)&Qs[row*QPAD + lc4] =
            *(const float4*)(qb + (size_t)(q0 + row)*DD + lc4);
    }

    MST_ISSUE(0, 0);

    float mx[8], sum[8];
#pragma unroll
    for (int s = 0; s < 8; s++) { mx[s] = -INFINITY; sum[s] = 0.f; }

    for (int nt = 0; nt < 16; nt++) {
        if (nt < 15) MST_ISSUE(nt + 1, (nt + 1) & 1);
        if (nt < 15) { CP_WAIT(1); } else { CP_WAIT(0); }
        __syncthreads();

        const float* Kp = sm + (1 + (nt & 1))*QTILE;

        float c[4][4][4];
#pragma unroll
        for (int i = 0; i < 4; i++)
#pragma unroll
            for (int j = 0; j < 4; j++)
#pragma unroll
                for (int r = 0; r < 4; r++) c[i][j][r] = 0.f;

#pragma unroll
        for (int kk = 0; kk < 8; kk++) {
            int kbs = kk * 8;
            uint32_t af[4][4];
#pragma unroll
            for (int mt = 0; mt < 4; mt++) {
                int base = (wm*64 + mt*16 + g)*QPAD + kbs + tig;
                af[mt][0] = __float_as_uint(Qs[base]);
                af[mt][1] = __float_as_uint(Qs[base + 8*QPAD]);
                af[mt][2] = __float_as_uint(Qs[base + 4]);
                af[mt][3] = __float_as_uint(Qs[base + 8*QPAD + 4]);
            }
            uint32_t bf[4][2];
#pragma unroll
            for (int nt2 = 0; nt2 < 4; nt2++) {
                int base = (wn*32 + nt2*8 + g)*QPAD + kbs + tig;
                bf[nt2][0] = __float_as_uint(Kp[base]);
                bf[nt2][1] = __float_as_uint(Kp[base + 4]);
            }
#pragma unroll
            for (int mt = 0; mt < 4; mt++)
#pragma unroll
                for (int nt2 = 0; nt2 < 4; nt2++)
                    mma_tf32(c[mt][nt2], af[mt], bf[nt2]);
        }

#pragma unroll
        for (int mt = 0; mt < 4; mt++)
#pragma unroll
            for (int nt2 = 0; nt2 < 4; nt2++) {
                mx[mt*2+0]  = fmaxf(mx[mt*2+0], fmaxf(c[mt][nt2][0], c[mt][nt2][1]));
                sum[mt*2+0] += c[mt][nt2][0] + c[mt][nt2][1];
                mx[mt*2+1]  = fmaxf(mx[mt*2+1], fmaxf(c[mt][nt2][2], c[mt][nt2][3]));
                sum[mt*2+1] += c[mt][nt2][2] + c[mt][nt2][3];
            }
        __syncthreads();
    }
#undef MST_ISSUE

#pragma unroll
    for (int s = 0; s < 8; s++) {
        mx[s]  = fmaxf(mx[s],  __shfl_xor_sync(0xffffffff, mx[s], 1));
        mx[s]  = fmaxf(mx[s],  __shfl_xor_sync(0xffffffff, mx[s], 2));
        sum[s] += __shfl_xor_sync(0xffffffff, sum[s], 1);
        sum[s] += __shfl_xor_sync(0xffffffff, sum[s], 2);
    }
    if (tig == 0) {
#pragma unroll
        for (int mt = 0; mt < 4; mt++)
#pragma unroll
            for (int hi = 0; hi < 2; hi++) {
                int row = wm*64 + mt*16 + g + hi*8;
                redm[wn*128 + row] = mx[mt*2+hi];
                reds[wn*128 + row] = sum[mt*2+hi];
            }
    }
    __syncthreads();
    if (t < 128) {
        float m = redm[t], s = reds[t];
#pragma unroll
        for (int x = 1; x < 4; x++) {
            m = fmaxf(m, redm[x*128 + t]);
            s += reds[x*128 + t];
        }
        g_M[(size_t)bh*LL + q0 + t] = SCALE * (m - s * (1.f/LL));
    }
}

// ---------------- top-U selection per (b,h), JAX tie-break (lower idx) -----
__global__ void topk_kernel() {
    __shared__ float vals[LL];
    __shared__ float rv[256];
    __shared__ int   ri[256];
    int t  = threadIdx.x;
    int bh = blockIdx.x;
    for (int i = t; i < LL; i += 256) vals[i] = g_M[(size_t)bh*LL + i];
    __syncthreads();
    for (int u = 0; u < UU; u++) {
        float bv = -INFINITY; int bi = 0x7fffffff;
        for (int i = t; i < LL; i += 256) {
            float v = vals[i];
            if (v > bv) { bv = v; bi = i; }
        }
        rv[t] = bv; ri[t] = bi;
        __syncthreads();
        for (int s = 128; s > 0; s >>= 1) {
            if (t < s) {
                float ov = rv[t+s]; int oi = ri[t+s];
                if (ov > rv[t] || (ov == rv[t] && oi < ri[t])) { rv[t] = ov; ri[t] = oi; }
            }
            __syncthreads();
        }
        if (t == 0) { g_topk[bh*UU + u] = ri[0]; vals[ri[0]] = -INFINITY; }
        __syncthreads();
    }
}

// =============== fused split-KV sparse attention ===========================
#define ATT_SMEM_FLOATS (2720 + 8704 + 8704 + 5280 + 120)
__global__ void __launch_bounds__(256) attn_part() {
    extern __shared__ float sm[];
    float* Qs = sm;
    float* Ks = sm + 2720;
    float* Vs = sm + 11424;
    float* S  = sm + 20128;
    float* Mv = sm + 25408;
    float* Al = sm + 25448;
    float* Lv = sm + 25488;

    int t = threadIdx.x;
    int split = blockIdx.x, bh = blockIdx.y;
    int b = bh >> 3, h = bh & 7;
    int w = t >> 5, l = t & 31;
    int j = t & 127, qs = t >> 7;
    int d = t & 63,  qg = t >> 6;

    for (int idx = t; idx < 640; idx += 256) {
        int u = idx >> 4, c4 = (idx & 15) * 4;
        int lq = g_topk[bh*UU + u];
        *(float4*)&Qs[u*68 + c4] =
            *(const float4*)&g_q[((size_t)(b*LL + lq))*DD + h*DHH + c4];
    }
    if (t < 40) { Mv[t] = -INFINITY; Lv[t] = 0.f; }

    float acc[10];
#pragma unroll
    for (int i = 0; i < 10; i++) acc[i] = 0.f;
    float vsum = 0.f;

    for (int tt = 0; tt < ATILES; tt++) {
        int n0 = (split*ATILES + tt) * 128;
        __syncthreads();
#pragma unroll
        for (int r = 0; r < 8; r++) {
            int idx = r*256 + t;
            int row = idx >> 4, c4 = (idx & 15) * 4;
            size_t gofs = ((size_t)(b*LL + n0 + row))*DD + h*DHH + c4;
            *(float4*)&Ks[row*68 + c4] = *(const float4*)&g_k[gofs];
            *(float4*)&Vs[row*68 + c4] = *(const float4*)&g_v[gofs];
        }
        __syncthreads();

        if (t < 64)
            for (int jj = 0; jj < 128; jj++) vsum += Vs[jj*68 + t];

        float s[20];
#pragma unroll
        for (int i = 0; i < 20; i++) s[i] = 0.f;
#pragma unroll
        for (int d4 = 0; d4 < 16; d4++) {
            float4 kv = *(float4*)&Ks[j*68 + d4*4];
#pragma unroll
            for (int i = 0; i < 20; i++) {
                float4 qv = *(float4*)&Qs[(qs + 2*i)*68 + d4*4];
                s[i] += qv.x*kv.x + qv.y*kv.y + qv.z*kv.z + qv.w*kv.w;
            }
        }
#pragma unroll
        for (int i = 0; i < 20; i++) S[(qs + 2*i)*132 + j] = s[i] * SCALE;
        __syncthreads();

#pragma unroll
        for (int r = 0; r < 5; r++) {
            int q = w*5 + r;
            float mxv = fmaxf(fmaxf(S[q*132 + l], S[q*132 + l + 32]),
                              fmaxf(S[q*132 + l + 64], S[q*132 + l + 96]));
#pragma unroll
            for (int o = 16; o; o >>= 1) mxv = fmaxf(mxv, __shfl_xor_sync(~0u, mxv, o));
            if (l == 0) {
                float mn = fmaxf(Mv[q], mxv);
                Al[q] = __expf(Mv[q] - mn);
                Mv[q] = mn;
            }
        }
        __syncthreads();

#pragma unroll
        for (int i = 0; i < 20; i++) {
            int q = qs + 2*i;
            S[q*132 + j] = __expf(S[q*132 + j] - Mv[q]);
        }
        __syncthreads();

#pragma unroll
        for (int r = 0; r < 5; r++) {
            int q = w*5 + r;
            float sme = S[q*132 + l] + S[q*132 + l + 32]
                      + S[q*132 + l + 64] + S[q*132 + l + 96];
#pragma unroll
            for (int o = 16; o; o >>= 1) sme += __shfl_xor_sync(~0u, sme, o);
            if (l == 0) Lv[q] = Lv[q]*Al[q] + sme;
        }
        // rescale accumulators, then PV with vectorized S reads
#pragma unroll
        for (int i = 0; i < 10; i++) acc[i] *= Al[qg + 4*i];
        for (int jj = 0; jj < 128; jj += 4) {
            float v0 = Vs[(jj+0)*68 + d];
            float v1 = Vs[(jj+1)*68 + d];
            float v2 = Vs[(jj+2)*68 + d];
            float v3 = Vs[(jj+3)*68 + d];
#pragma unroll
            for (int i = 0; i < 10; i++) {
                float4 s4 = *(float4*)&S[(qg + 4*i)*132 + jj];
                acc[i] += s4.x*v0 + s4.y*v1 + s4.z*v2 + s4.w*v3;
            }
        }
    }
    __syncthreads();

    int base = bh*ASPLIT + split;
#pragma unroll
    for (int i = 0; i < 10; i++)
        g_pacc[((size_t)base*UU + qg + 4*i)*DHH + d] = acc[i];
    if (t < 40) { g_pm[base*UU + t] = Mv[t]; g_pl[base*UU + t] = Lv[t]; }
    if (t < 64) g_pvs[base*DHH + t] = vsum;
}

__global__ void vmean_combine() {
    int bh = blockIdx.x, t = threadIdx.x;     // <<<32, 64>>>
    int b = bh >> 3, h = bh & 7;
    float s = 0.f;
#pragma unroll
    for (int sp = 0; sp < ASPLIT; sp++) s += g_pvs[(bh*ASPLIT + sp)*DHH + t];
    g_vmean[b*DD + h*DHH + t] = s;
}

__global__ void ctx_fill_kernel() {
    int row = blockIdx.x;
    int d   = blockIdx.y*256 + threadIdx.x;
    int b   = row >> 11;
    g_ctx[(size_t)row*DD + d] = g_vmean[b*DD + d] * (1.f/LL);
}

__global__ void attn_combine() {
    int t = threadIdx.x, bh = blockIdx.x;     // <<<32, 256>>>
    int b = bh >> 3, h = bh & 7;
    int d = t & 63, qg = t >> 6;
#pragma unroll
    for (int i = 0; i < 10; i++) {
        int q = qg + 4*i;
        float ms[ASPLIT], M = -INFINITY;
#pragma unroll
        for (int s = 0; s < ASPLIT; s++) {
            ms[s] = g_pm[(bh*ASPLIT + s)*UU + q];
            M = fmaxf(M, ms[s]);
        }
        float L = 0.f, o = 0.f;
#pragma unroll
        for (int s = 0; s < ASPLIT; s++) {
            float wv = __expf(ms[s] - M);
            L += g_pl[(bh*ASPLIT + s)*UU + q] * wv;
            o += g_pacc[((size_t)(bh*ASPLIT + s)*UU + q)*DHH + d] * wv;
        }
        int lq = g_topk[bh*UU + q];
        g_ctx[((size_t)(b*LL + lq))*DD + h*DHH + d] = o / L;
    }
}

// ---------------- residual + LayerNorm (single-pass sum/sumsq) -------------
__global__ void lnres_kernel(const float* __restrict__ delta,
                             const float* __restrict__ gam,
                             const float* __restrict__ bet) {
    int row = blockIdx.x;
    int t   = threadIdx.x, w = t >> 5, l = t & 31;
    __shared__ float ss[8], qq[8];
    float v0 = g_h[(size_t)row*DD + t]       + delta[(size_t)row*DD + t];
    float v1 = g_h[(size_t)row*DD + t + 256] + delta[(size_t)row*DD + t + 256];
    float s = v0 + v1;
    float q = v0*v0 + v1*v1;
#pragma unroll
    for (int o = 16; o; o >>= 1) {
        s += __shfl_xor_sync(~0u, s, o);
        q += __shfl_xor_sync(~0u, q, o);
    }
    if (l == 0) { ss[w] = s; qq[w] = q; }
    __syncthreads();
    float S = 0.f, Q = 0.f;
#pragma unroll
    for (int i = 0; i < 8; i++) { S += ss[i]; Q += qq[i]; }
    float mean = S * (1.f/DD);
    float var  = Q * (1.f/DD) - mean*mean;
    float inv = rsqrtf(var + 1e-5f);
    g_h[(size_t)row*DD + t]       = (v0 - mean)*inv*gam[t]     + bet[t];
    g_h[(size_t)row*DD + t + 256] = (v1 - mean)*inv*gam[t+256] + bet[t+256];
}

// ---------------- final projection -----------------------------------------
__global__ void proj_kernel(const float* __restrict__ w,
                            const float* __restrict__ b,
                            float* __restrict__ out) {
    int t  = threadIdx.x, wr = t >> 5, l = t & 31;
    int bp = blockIdx.x;
    int bb = bp / PP, p = bp % PP;
    int row = bb*LL + (LL - PP) + p;
    float acc[EE];
#pragma unroll
    for (int e = 0; e < EE; e++) acc[e] = 0.f;
    for (int d = t; d < DD; d += 256) {
        float hv = g_h[(size_t)row*DD + d];
#pragma unroll
        for (int e = 0; e < EE; e++) acc[e] += hv * w[d*EE + e];
    }
    __shared__ float red[8][EE];
#pragma unroll
    for (int e = 0; e < EE; e++) {
#pragma unroll
        for (int o = 16; o; o >>= 1) acc[e] += __shfl_xor_sync(~0u, acc[e], o);
        if (l == 0) red[wr][e] = acc[e];
    }
    __syncthreads();
    if (t < EE) {
        float s = 0.f;
#pragma unroll
        for (int i = 0; i < 8; i++) s += red[i][t];
        out[bp*EE + t] = s + b[t];
    }
}

// ---------------- host orchestration ---------------------------------------
extern "C" void kernel_launch(void* const* d_in, const int* in_sizes, int n_in,
                              void* d_out, int out_size) {
    const float* x      = (const float*)d_in[0];
    const float* emb_w  = (const float*)d_in[1];
    const float* emb_b  = (const float*)d_in[2];
    const float* Wq     = (const float*)d_in[3];
    const float* bq     = (const float*)d_in[4];
    const float* Wk     = (const float*)d_in[5];
    const float* bk     = (const float*)d_in[6];
    const float* Wv     = (const float*)d_in[7];
    const float* bv     = (const float*)d_in[8];
    const float* Wo     = (const float*)d_in[9];
    const float* bo     = (const float*)d_in[10];
    const float* W1     = (const float*)d_in[11];
    const float* b1     = (const float*)d_in[12];
    const float* W2     = (const float*)d_in[13];
    const float* b2     = (const float*)d_in[14];
    const float* ln1_g  = (const float*)d_in[15];
    const float* ln1_b  = (const float*)d_in[16];
    const float* ln2_g  = (const float*)d_in[17];
    const float* ln2_b  = (const float*)d_in[18];
    const float* proj_w = (const float*)d_in[19];
    const float* proj_b = (const float*)d_in[20];
    float* out = (float*)d_out;

    float *ph, *pctx, *pt1, *pt2, *pwt;
    cudaGetSymbolAddress((void**)&ph,   g_h);
    cudaGetSymbolAddress((void**)&pctx, g_ctx);
    cudaGetSymbolAddress((void**)&pt1,  g_t1);
    cudaGetSymbolAddress((void**)&pt2,  g_t2);
    cudaGetSymbolAddress((void**)&pwt,  g_wt);

    const int GEMM_SMEM   = 2*GSTAGE*GBUF*sizeof(float);       // 110592
    const int MSTATS_SMEM = (3*QTILE + 1024)*sizeof(float);    // 108544
    const int ATT_SMEM    = ATT_SMEM_FLOATS*sizeof(float);     // 102112
    cudaFuncSetAttribute(gemm_mma,   cudaFuncAttributeMaxDynamicSharedMemorySize, GEMM_SMEM);
    cudaFuncSetAttribute(gemm_qkv,   cudaFuncAttributeMaxDynamicSharedMemorySize, GEMM_SMEM);
    cudaFuncSetAttribute(mstats_mma, cudaFuncAttributeMaxDynamicSharedMemorySize, MSTATS_SMEM);
    cudaFuncSetAttribute(attn_part,  cudaFuncAttributeMaxDynamicSharedMemorySize, ATT_SMEM);

    transpose_all<<<dim3(16, 16, 12), dim3(32, 8)>>>(Wq, Wk, Wv, Wo, W1, W2);
    embed_kernel<<<dim3(BL, DD/256), 256>>>(x, emb_w, emb_b);

    dim3 ggrid(DD/128, BL/128);       // (4, 64)

    for (int lay = 0; lay < NLL; lay++) {
        float* tWo = pwt + (size_t)(lay*6 + 3)*DD*DD;
        float* tW1 = pwt + (size_t)(lay*6 + 4)*DD*DD;
        float* tW2 = pwt + (size_t)(lay*6 + 5)*DD*DD;

        gemm_qkv<<<dim3(DD/128, BL/128, 3), 256, GEMM_SMEM>>>(
            lay, bq + lay*DD, bk + lay*DD, bv + lay*DD);

        mstats_mma<<<dim3(LL/128, BB*HH), 256, MSTATS_SMEM>>>();
        topk_kernel<<<BB*HH, 256>>>();

        attn_part<<<dim3(ASPLIT, BB*HH), 256, ATT_SMEM>>>();
        vmean_combine<<<BB*HH, 64>>>();
        ctx_fill_kernel<<<dim3(BL, DD/256), 256>>>();
        attn_combine<<<BB*HH, 256>>>();

        gemm_mma<<<ggrid, 256, GEMM_SMEM>>>(pctx, tWo, bo + lay*DD, pt1, 0);
        lnres_kernel<<<BL, 256>>>(pt1, ln1_g + lay*DD, ln1_b + lay*DD);

        gemm_mma<<<ggrid, 256, GEMM_SMEM>>>(ph, tW1, b1 + lay*DD, pt1, 1);
        gemm_mma<<<ggrid, 256, GEMM_SMEM>>>(pt1, tW2, b2 + lay*DD, pt2, 0);
        lnres_kernel<<<BL, 256>>>(pt2, ln2_g + lay*DD, ln2_b + lay*DD);
    }

    proj_kernel<<<BB*PP, 256>>>(proj_w, proj_b, out);
}

// round 6
// speedup vs baseline: 3.3090x; 1.0270x over previous
#include <cuda_runtime.h>
#include <math.h>
#include <cstdint>

// Problem constants
#define BB   4
#define LL   2048
#define EE   7
#define DD   512
#define HH   8
#define DHH  64
#define PP   720
#define NLL  2
#define UU   40
#define BL   (BB*LL)          // 8192 rows
#define SCALE 0.125f          // 1/sqrt(64)
#define ASPLIT 8
#define ATILES (16/ASPLIT)    // key tiles of 128 per split block

// ---------------- scratch (device globals; no allocation allowed) ----------
__device__ float g_h[BL*DD];
__device__ float g_q[BL*DD];
__device__ float g_k[BL*DD];
__device__ float g_v[BL*DD];
__device__ float g_ctx[BL*DD];
__device__ float g_t1[BL*DD];
__device__ float g_t2[BL*DD];
__device__ float g_M[BB*HH*LL];
__device__ float g_vmean[BB*DD];
__device__ int   g_topk[BB*HH*UU];
__device__ float g_wt[12*DD*DD];            // transposed weights, [n][k], tf32-rounded
__device__ float g_pacc[32*ASPLIT*UU*DHH];  // split-KV partial outputs
__device__ float g_pm[32*ASPLIT*UU];
__device__ float g_pl[32*ASPLIT*UU];
__device__ float g_pvs[32*ASPLIT*DHH];      // partial V column sums

// ---------------- helpers ---------------------------------------------------
__device__ __forceinline__ float totf32(float x) {
    uint32_t r;
    asm("cvt.rna.tf32.f32 %0, %1;" : "=r"(r) : "f"(x));
    return __uint_as_float(r);
}
__device__ __forceinline__ void mma_tf32(float c[4], const uint32_t a[4], const uint32_t b[2]) {
    asm volatile("mma.sync.aligned.m16n8k8.row.col.f32.tf32.tf32.f32 "
        "{%0,%1,%2,%3}, {%4,%5,%6,%7}, {%8,%9}, {%0,%1,%2,%3};"
        : "+f"(c[0]), "+f"(c[1]), "+f"(c[2]), "+f"(c[3])
        : "r"(a[0]), "r"(a[1]), "r"(a[2]), "r"(a[3]), "r"(b[0]), "r"(b[1]));
}
__device__ __forceinline__ uint32_t smem_u32(const void* p) {
    uint32_t a;
    asm("{ .reg .u64 t; cvta.to.shared.u64 t, %1; cvt.u32.u64 %0, t; }" : "=r"(a) : "l"(p));
    return a;
}
__device__ __forceinline__ void cp_async16(uint32_t s, const void* g) {
    asm volatile("cp.async.cg.shared.global [%0], [%1], 16;" :: "r"(s), "l"(g));
}
#define CP_COMMIT() asm volatile("cp.async.commit_group;" ::: "memory")
#define CP_WAIT(n)  asm volatile("cp.async.wait_group %0;" :: "n"(n) : "memory")

// ---------------- batched weight transpose: Wt[n][k] = tf32(W[k][n]) -------
__global__ void transpose_all(const float* __restrict__ Wq, const float* __restrict__ Wk,
                              const float* __restrict__ Wv, const float* __restrict__ Wo,
                              const float* __restrict__ W1, const float* __restrict__ W2) {
    __shared__ float tile[32][33];
    int z = blockIdx.z;
    int lay = z / 6, j = z % 6;
    const float* W = (j==0?Wq : j==1?Wk : j==2?Wv : j==3?Wo : j==4?W1 : W2)
                     + (size_t)lay*DD*DD;
    float* Wt = g_wt + (size_t)z*DD*DD;
    int x0 = blockIdx.x*32, y0 = blockIdx.y*32;
    int tx = threadIdx.x, ty = threadIdx.y;   // (32,8)
#pragma unroll
    for (int jj = 0; jj < 32; jj += 8)
        tile[ty+jj][tx] = W[(size_t)(y0+ty+jj)*DD + x0+tx];
    __syncthreads();
#pragma unroll
    for (int jj = 0; jj < 32; jj += 8)
        Wt[(size_t)(x0+ty+jj)*DD + y0+tx] = totf32(tile[tx][ty+jj]);
}

// ---------------- embedding: h = x @ emb_w + emb_b -------------------------
__global__ void embed_kernel(const float* __restrict__ x,
                             const float* __restrict__ w,
                             const float* __restrict__ b) {
    int row = blockIdx.x;
    int d   = blockIdx.y * 256 + threadIdx.x;
    __shared__ float xs[EE];
    if (threadIdx.x < EE) xs[threadIdx.x] = x[row*EE + threadIdx.x];
    __syncthreads();
    float acc = b[d];
#pragma unroll
    for (int e = 0; e < EE; e++) acc += xs[e] * w[e*DD + d];
    g_h[(size_t)row*DD + d] = acc;
}

// =============== tf32 mma.sync GEMM (cp.async 3-stage) =====================
#define GPAD 36
#define GBUF (128*GPAD)
#define GSTAGE 3
__device__ __forceinline__ void gemm_body(const float* __restrict__ A,
                                          const float* __restrict__ Bt,
                                          const float* __restrict__ bias,
                                          float* __restrict__ C, int relu,
                                          float* sm) {
    int t = threadIdx.x, l = t & 31, w = t >> 5;
    int g = l >> 2, tig = l & 3;
    int wm = w >> 2, wn = w & 3;
    int m0 = blockIdx.y * 128, n0 = blockIdx.x * 128;

    const float* Ab = A  + (size_t)m0 * DD;
    const float* Bb = Bt + (size_t)n0 * DD;

    uint32_t sA = smem_u32(sm);
    uint32_t sB = sA + GSTAGE*GBUF*4;

    int irow = t >> 3;
    int ic = (t & 7) * 4;
#define GEMM_ISSUE(chunk, stage) do {                                          \
        int _k0 = (chunk) * 32;                                                \
        uint32_t _oa = sA + (uint32_t)(stage)*GBUF*4;                          \
        uint32_t _ob = sB + (uint32_t)(stage)*GBUF*4;                          \
        _Pragma("unroll")                                                      \
        for (int _r = 0; _r < 4; _r++) {                                       \
            int _row = _r*32 + irow;                                           \
            uint32_t _so = (uint32_t)(_row*GPAD + ic)*4;                       \
            cp_async16(_oa + _so, Ab + (size_t)_row*DD + _k0 + ic);            \
            cp_async16(_ob + _so, Bb + (size_t)_row*DD + _k0 + ic);            \
        }                                                                      \
        CP_COMMIT();                                                           \
    } while (0)

    float c[4][4][4];
#pragma unroll
    for (int i = 0; i < 4; i++)
#pragma unroll
        for (int j = 0; j < 4; j++)
#pragma unroll
            for (int r = 0; r < 4; r++) c[i][j][r] = 0.f;

    GEMM_ISSUE(0, 0);
    GEMM_ISSUE(1, 1);

    for (int chunk = 0; chunk < 16; chunk++) {
        if (chunk < 15) { CP_WAIT(1); } else { CP_WAIT(0); }
        __syncthreads();
        if (chunk + 2 < 16) GEMM_ISSUE(chunk + 2, (chunk + 2) % GSTAGE);

        const float* Ap = sm + (chunk % GSTAGE)*GBUF;
        const float* Bp = sm + (GSTAGE + chunk % GSTAGE)*GBUF;
#pragma unroll
        for (int kk = 0; kk < 4; kk++) {
            int kb = kk * 8;
            uint32_t af[4][4];
#pragma unroll
            for (int mt = 0; mt < 4; mt++) {
                int base = (wm*64 + mt*16 + g)*GPAD + kb + tig;
                af[mt][0] = __float_as_uint(Ap[base]);
                af[mt][1] = __float_as_uint(Ap[base + 8*GPAD]);
                af[mt][2] = __float_as_uint(Ap[base + 4]);
                af[mt][3] = __float_as_uint(Ap[base + 8*GPAD + 4]);
            }
            uint32_t bf[4][2];
#pragma unroll
            for (int nt = 0; nt < 4; nt++) {
                int base = (wn*32 + nt*8 + g)*GPAD + kb + tig;
                bf[nt][0] = __float_as_uint(Bp[base]);
                bf[nt][1] = __float_as_uint(Bp[base + 4]);
            }
#pragma unroll
            for (int mt = 0; mt < 4; mt++)
#pragma unroll
                for (int nt = 0; nt < 4; nt++)
                    mma_tf32(c[mt][nt], af[mt], bf[nt]);
        }
        __syncthreads();
    }

#pragma unroll
    for (int mt = 0; mt < 4; mt++) {
        int row = m0 + wm*64 + mt*16 + g;
#pragma unroll
        for (int nt = 0; nt < 4; nt++) {
            int col = n0 + wn*32 + nt*8 + 2*tig;
            float b0 = bias[col], b1 = bias[col+1];
            float2 v0 = make_float2(c[mt][nt][0] + b0, c[mt][nt][1] + b1);
            float2 v1 = make_float2(c[mt][nt][2] + b0, c[mt][nt][3] + b1);
            if (relu) {
                v0.x = fmaxf(v0.x, 0.f); v0.y = fmaxf(v0.y, 0.f);
                v1.x = fmaxf(v1.x, 0.f); v1.y = fmaxf(v1.y, 0.f);
            }
            *(float2*)(C + (size_t)row*DD + col)     = v0;
            *(float2*)(C + (size_t)(row+8)*DD + col) = v1;
        }
    }
#undef GEMM_ISSUE
}

__global__ void __launch_bounds__(256, 2) gemm_mma(const float* __restrict__ A,
                                                   const float* __restrict__ Bt,
                                                   const float* __restrict__ bias,
                                                   float* __restrict__ C, int relu) {
    extern __shared__ float sm[];
    gemm_body(A, Bt, bias, C, relu, sm);
}

__global__ void __launch_bounds__(256, 2) gemm_qkv(int lay,
                                                   const float* __restrict__ bq,
                                                   const float* __restrict__ bk,
                                                   const float* __restrict__ bv) {
    extern __shared__ float sm[];
    int z = blockIdx.z;
    const float* Bt = g_wt + (size_t)(lay*6 + z)*DD*DD;
    const float* bias = (z==0) ? bq : (z==1) ? bk : bv;
    float* C = (z==0) ? g_q : (z==1) ? g_k : g_v;
    gemm_body(g_h, Bt, bias, C, 0, sm);
}

// ========= score stats: M = SCALE*(max - mean), cp.async double-buffer =====
#define QPAD 68
#define QTILE (128*QPAD)
__global__ void __launch_bounds__(256, 2) mstats_mma() {
    extern __shared__ float sm[];
    float* Qs   = sm;                     // [128][QPAD]
    float* redm = sm + 3*QTILE;           // [4][128]
    float* reds = sm + 3*QTILE + 512;

    int t = threadIdx.x, w = t >> 5, l = t & 31;
    int g = l >> 2, tig = l & 3;
    int wm = w >> 2, wn = w & 3;
    int bh = blockIdx.y, b = bh >> 3, h = bh & 7;
    int q0 = blockIdx.x * 128;

    const float* qb = g_q + (size_t)b*LL*DD + h*DHH;
    const float* kb = g_k + (size_t)b*LL*DD + h*DHH;

    uint32_t sK = smem_u32(sm) + QTILE*4;     // 2 stages of [128][QPAD]

    int lrow8 = t >> 4;           // 0..15
    int lc4   = (t & 15) * 4;

#define MST_ISSUE(nt, stage) do {                                              \
        int _n0 = (nt) * 128;                                                  \
        uint32_t _ok = sK + (uint32_t)(stage)*QTILE*4;                         \
        _Pragma("unroll")                                                      \
        for (int _r = 0; _r < 8; _r++) {                                       \
            int _row = _r*16 + lrow8;                                          \
            cp_async16(_ok + (uint32_t)(_row*QPAD + lc4)*4,                    \
                       kb + (size_t)(_n0 + _row)*DD + lc4);                    \
        }                                                                      \
        CP_COMMIT();                                                           \
    } while (0)

#pragma unroll
    for (int r = 0; r < 8; r++) {
        int row = r*16 + lrow8;
        *(float4*)&Qs[row*QPAD + lc4] =
            *(const float4*)(qb + (size_t)(q0 + row)*DD + lc4);
    }

    MST_ISSUE(0, 0);

    float mx[8], sum[8];
#pragma unroll
    for (int s = 0; s < 8; s++) { mx[s] = -INFINITY; sum[s] = 0.f; }

    for (int nt = 0; nt < 16; nt++) {
        if (nt < 15) MST_ISSUE(nt + 1, (nt + 1) & 1);
        if (nt < 15) { CP_WAIT(1); } else { CP_WAIT(0); }
        __syncthreads();

        const float* Kp = sm + (1 + (nt & 1))*QTILE;

        float c[4][4][4];
#pragma unroll
        for (int i = 0; i < 4; i++)
#pragma unroll
            for (int j = 0; j < 4; j++)
#pragma unroll
                for (int r = 0; r < 4; r++) c[i][j][r] = 0.f;

#pragma unroll
        for (int kk = 0; kk < 8; kk++) {
            int kbs = kk * 8;
            uint32_t af[4][4];
#pragma unroll
            for (int mt = 0; mt < 4; mt++) {
                int base = (wm*64 + mt*16 + g)*QPAD + kbs + tig;
                af[mt][0] = __float_as_uint(Qs[base]);
                af[mt][1] = __float_as_uint(Qs[base + 8*QPAD]);
                af[mt][2] = __float_as_uint(Qs[base + 4]);
                af[mt][3] = __float_as_uint(Qs[base + 8*QPAD + 4]);
            }
            uint32_t bf[4][2];
#pragma unroll
            for (int nt2 = 0; nt2 < 4; nt2++) {
                int base = (wn*32 + nt2*8 + g)*QPAD + kbs + tig;
                bf[nt2][0] = __float_as_uint(Kp[base]);
                bf[nt2][1] = __float_as_uint(Kp[base + 4]);
            }
#pragma unroll
            for (int mt = 0; mt < 4; mt++)
#pragma unroll
                for (int nt2 = 0; nt2 < 4; nt2++)
                    mma_tf32(c[mt][nt2], af[mt], bf[nt2]);
        }

#pragma unroll
        for (int mt = 0; mt < 4; mt++)
#pragma unroll
            for (int nt2 = 0; nt2 < 4; nt2++) {
                mx[mt*2+0]  = fmaxf(mx[mt*2+0], fmaxf(c[mt][nt2][0], c[mt][nt2][1]));
                sum[mt*2+0] += c[mt][nt2][0] + c[mt][nt2][1];
                mx[mt*2+1]  = fmaxf(mx[mt*2+1], fmaxf(c[mt][nt2][2], c[mt][nt2][3]));
                sum[mt*2+1] += c[mt][nt2][2] + c[mt][nt2][3];
            }
        __syncthreads();
    }
#undef MST_ISSUE

#pragma unroll
    for (int s = 0; s < 8; s++) {
        mx[s]  = fmaxf(mx[s],  __shfl_xor_sync(0xffffffff, mx[s], 1));
        mx[s]  = fmaxf(mx[s],  __shfl_xor_sync(0xffffffff, mx[s], 2));
        sum[s] += __shfl_xor_sync(0xffffffff, sum[s], 1);
        sum[s] += __shfl_xor_sync(0xffffffff, sum[s], 2);
    }
    if (tig == 0) {
#pragma unroll
        for (int mt = 0; mt < 4; mt++)
#pragma unroll
            for (int hi = 0; hi < 2; hi++) {
                int row = wm*64 + mt*16 + g + hi*8;
                redm[wn*128 + row] = mx[mt*2+hi];
                reds[wn*128 + row] = sum[mt*2+hi];
            }
    }
    __syncthreads();
    if (t < 128) {
        float m = redm[t], s = reds[t];
#pragma unroll
        for (int x = 1; x < 4; x++) {
            m = fmaxf(m, redm[x*128 + t]);
            s += reds[x*128 + t];
        }
        g_M[(size_t)bh*LL + q0 + t] = SCALE * (m - s * (1.f/LL));
    }
}

// ---------------- top-U selection per (b,h), JAX tie-break (lower idx) -----
__global__ void topk_kernel() {
    __shared__ float vals[LL];
    __shared__ float rv[256];
    __shared__ int   ri[256];
    int t  = threadIdx.x;
    int bh = blockIdx.x;
    for (int i = t; i < LL; i += 256) vals[i] = g_M[(size_t)bh*LL + i];
    __syncthreads();
    for (int u = 0; u < UU; u++) {
        float bv = -INFINITY; int bi = 0x7fffffff;
        for (int i = t; i < LL; i += 256) {
            float v = vals[i];
            if (v > bv) { bv = v; bi = i; }
        }
        rv[t] = bv; ri[t] = bi;
        __syncthreads();
        for (int s = 128; s > 0; s >>= 1) {
            if (t < s) {
                float ov = rv[t+s]; int oi = ri[t+s];
                if (ov > rv[t] || (ov == rv[t] && oi < ri[t])) { rv[t] = ov; ri[t] = oi; }
            }
            __syncthreads();
        }
        if (t == 0) { g_topk[bh*UU + u] = ri[0]; vals[ri[0]] = -INFINITY; }
        __syncthreads();
    }
}

// =============== fused split-KV sparse attention ===========================
#define ATT_SMEM_FLOATS (2720 + 8704 + 8704 + 5280 + 120)
__global__ void __launch_bounds__(256, 2) attn_part() {
    extern __shared__ float sm[];
    float* Qs = sm;
    float* Ks = sm + 2720;
    float* Vs = sm + 11424;
    float* S  = sm + 20128;
    float* Mv = sm + 25408;
    float* Al = sm + 25448;
    float* Lv = sm + 25488;

    int t = threadIdx.x;
    int split = blockIdx.x, bh = blockIdx.y;
    int b = bh >> 3, h = bh & 7;
    int w = t >> 5, l = t & 31;
    int j = t & 127, qs = t >> 7;
    int d = t & 63,  qg = t >> 6;

    for (int idx = t; idx < 640; idx += 256) {
        int u = idx >> 4, c4 = (idx & 15) * 4;
        int lq = g_topk[bh*UU + u];
        *(float4*)&Qs[u*68 + c4] =
            *(const float4*)&g_q[((size_t)(b*LL + lq))*DD + h*DHH + c4];
    }
    if (t < 40) { Mv[t] = -INFINITY; Lv[t] = 0.f; }

    float acc[10];
#pragma unroll
    for (int i = 0; i < 10; i++) acc[i] = 0.f;
    float vsum = 0.f;

    for (int tt = 0; tt < ATILES; tt++) {
        int n0 = (split*ATILES + tt) * 128;
        __syncthreads();
#pragma unroll
        for (int r = 0; r < 8; r++) {
            int idx = r*256 + t;
            int row = idx >> 4, c4 = (idx & 15) * 4;
            size_t gofs = ((size_t)(b*LL + n0 + row))*DD + h*DHH + c4;
            *(float4*)&Ks[row*68 + c4] = *(const float4*)&g_k[gofs];
            *(float4*)&Vs[row*68 + c4] = *(const float4*)&g_v[gofs];
        }
        __syncthreads();

        if (t < 64)
            for (int jj = 0; jj < 128; jj++) vsum += Vs[jj*68 + t];

        float s[20];
#pragma unroll
        for (int i = 0; i < 20; i++) s[i] = 0.f;
#pragma unroll
        for (int d4 = 0; d4 < 16; d4++) {
            float4 kv = *(float4*)&Ks[j*68 + d4*4];
#pragma unroll
            for (int i = 0; i < 20; i++) {
                float4 qv = *(float4*)&Qs[(qs + 2*i)*68 + d4*4];
                s[i] += qv.x*kv.x + qv.y*kv.y + qv.z*kv.z + qv.w*kv.w;
            }
        }
#pragma unroll
        for (int i = 0; i < 20; i++) S[(qs + 2*i)*132 + j] = s[i] * SCALE;
        __syncthreads();

#pragma unroll
        for (int r = 0; r < 5; r++) {
            int q = w*5 + r;
            float mxv = fmaxf(fmaxf(S[q*132 + l], S[q*132 + l + 32]),
                              fmaxf(S[q*132 + l + 64], S[q*132 + l + 96]));
#pragma unroll
            for (int o = 16; o; o >>= 1) mxv = fmaxf(mxv, __shfl_xor_sync(~0u, mxv, o));
            if (l == 0) {
                float mn = fmaxf(Mv[q], mxv);
                Al[q] = __expf(Mv[q] - mn);
                Mv[q] = mn;
            }
        }
        __syncthreads();

#pragma unroll
        for (int i = 0; i < 20; i++) {
            int q = qs + 2*i;
            S[q*132 + j] = __expf(S[q*132 + j] - Mv[q]);
        }
        __syncthreads();

#pragma unroll
        for (int r = 0; r < 5; r++) {
            int q = w*5 + r;
            float sme = S[q*132 + l] + S[q*132 + l + 32]
                      + S[q*132 + l + 64] + S[q*132 + l + 96];
#pragma unroll
            for (int o = 16; o; o >>= 1) sme += __shfl_xor_sync(~0u, sme, o);
            if (l == 0) Lv[q] = Lv[q]*Al[q] + sme;
        }
#pragma unroll
        for (int i = 0; i < 10; i++) acc[i] *= Al[qg + 4*i];
        for (int jj = 0; jj < 128; jj += 4) {
            float v0 = Vs[(jj+0)*68 + d];
            float v1 = Vs[(jj+1)*68 + d];
            float v2 = Vs[(jj+2)*68 + d];
            float v3 = Vs[(jj+3)*68 + d];
#pragma unroll
            for (int i = 0; i < 10; i++) {
                float4 s4 = *(float4*)&S[(qg + 4*i)*132 + jj];
                acc[i] += s4.x*v0 + s4.y*v1 + s4.z*v2 + s4.w*v3;
            }
        }
    }
    __syncthreads();

    int base = bh*ASPLIT + split;
#pragma unroll
    for (int i = 0; i < 10; i++)
        g_pacc[((size_t)base*UU + qg + 4*i)*DHH + d] = acc[i];
    if (t < 40) { g_pm[base*UU + t] = Mv[t]; g_pl[base*UU + t] = Lv[t]; }
    if (t < 64) g_pvs[base*DHH + t] = vsum;
}

__global__ void vmean_combine() {
    int bh = blockIdx.x, t = threadIdx.x;     // <<<32, 64>>>
    int b = bh >> 3, h = bh & 7;
    float s = 0.f;
#pragma unroll
    for (int sp = 0; sp < ASPLIT; sp++) s += g_pvs[(bh*ASPLIT + sp)*DHH + t];
    g_vmean[b*DD + h*DHH + t] = s;
}

__global__ void ctx_fill_kernel() {
    int row = blockIdx.x;
    int d   = blockIdx.y*256 + threadIdx.x;
    int b   = row >> 11;
    g_ctx[(size_t)row*DD + d] = g_vmean[b*DD + d] * (1.f/LL);
}

__global__ void attn_combine() {
    int t = threadIdx.x, bh = blockIdx.x;     // <<<32, 256>>>
    int b = bh >> 3, h = bh & 7;
    int d = t & 63, qg = t >> 6;
#pragma unroll
    for (int i = 0; i < 10; i++) {
        int q = qg + 4*i;
        float ms[ASPLIT], M = -INFINITY;
#pragma unroll
        for (int s = 0; s < ASPLIT; s++) {
            ms[s] = g_pm[(bh*ASPLIT + s)*UU + q];
            M = fmaxf(M, ms[s]);
        }
        float L = 0.f, o = 0.f;
#pragma unroll
        for (int s = 0; s < ASPLIT; s++) {
            float wv = __expf(ms[s] - M);
            L += g_pl[(bh*ASPLIT + s)*UU + q] * wv;
            o += g_pacc[((size_t)(bh*ASPLIT + s)*UU + q)*DHH + d] * wv;
        }
        int lq = g_topk[bh*UU + q];
        g_ctx[((size_t)(b*LL + lq))*DD + h*DHH + d] = o / L;
    }
}

// ---------------- residual + LayerNorm (single-pass sum/sumsq) -------------
__global__ void lnres_kernel(const float* __restrict__ delta,
                             const float* __restrict__ gam,
                             const float* __restrict__ bet) {
    int row = blockIdx.x;
    int t   = threadIdx.x, w = t >> 5, l = t & 31;
    __shared__ float ss[8], qq[8];
    float v0 = g_h[(size_t)row*DD + t]       + delta[(size_t)row*DD + t];
    float v1 = g_h[(size_t)row*DD + t + 256] + delta[(size_t)row*DD + t + 256];
    float s = v0 + v1;
    float q = v0*v0 + v1*v1;
#pragma unroll
    for (int o = 16; o; o >>= 1) {
        s += __shfl_xor_sync(~0u, s, o);
        q += __shfl_xor_sync(~0u, q, o);
    }
    if (l == 0) { ss[w] = s; qq[w] = q; }
    __syncthreads();
    float S = 0.f, Q = 0.f;
#pragma unroll
    for (int i = 0; i < 8; i++) { S += ss[i]; Q += qq[i]; }
    float mean = S * (1.f/DD);
    float var  = Q * (1.f/DD) - mean*mean;
    float inv = rsqrtf(var + 1e-5f);
    g_h[(size_t)row*DD + t]       = (v0 - mean)*inv*gam[t]     + bet[t];
    g_h[(size_t)row*DD + t + 256] = (v1 - mean)*inv*gam[t+256] + bet[t+256];
}

// ---------------- final projection -----------------------------------------
__global__ void proj_kernel(const float* __restrict__ w,
                            const float* __restrict__ b,
                            float* __restrict__ out) {
    int t  = threadIdx.x, wr = t >> 5, l = t & 31;
    int bp = blockIdx.x;
    int bb = bp / PP, p = bp % PP;
    int row = bb*LL + (LL - PP) + p;
    float acc[EE];
#pragma unroll
    for (int e = 0; e < EE; e++) acc[e] = 0.f;
    for (int d = t; d < DD; d += 256) {
        float hv = g_h[(size_t)row*DD + d];
#pragma unroll
        for (int e = 0; e < EE; e++) acc[e] += hv * w[d*EE + e];
    }
    __shared__ float red[8][EE];
#pragma unroll
    for (int e = 0; e < EE; e++) {
#pragma unroll
        for (int o = 16; o; o >>= 1) acc[e] += __shfl_xor_sync(~0u, acc[e], o);
        if (l == 0) red[wr][e] = acc[e];
    }
    __syncthreads();
    if (t < EE) {
        float s = 0.f;
#pragma unroll
        for (int i = 0; i < 8; i++) s += red[i][t];
        out[bp*EE + t] = s + b[t];
    }
}

// ---------------- host orchestration ---------------------------------------
extern "C" void kernel_launch(void* const* d_in, const int* in_sizes, int n_in,
                              void* d_out, int out_size) {
    const float* x      = (const float*)d_in[0];
    const float* emb_w  = (const float*)d_in[1];
    const float* emb_b  = (const float*)d_in[2];
    const float* Wq     = (const float*)d_in[3];
    const float* bq     = (const float*)d_in[4];
    const float* Wk     = (const float*)d_in[5];
    const float* bk     = (const float*)d_in[6];
    const float* Wv     = (const float*)d_in[7];
    const float* bv     = (const float*)d_in[8];
    const float* Wo     = (const float*)d_in[9];
    const float* bo     = (const float*)d_in[10];
    const float* W1     = (const float*)d_in[11];
    const float* b1     = (const float*)d_in[12];
    const float* W2     = (const float*)d_in[13];
    const float* b2     = (const float*)d_in[14];
    const float* ln1_g  = (const float*)d_in[15];
    const float* ln1_b  = (const float*)d_in[16];
    const float* ln2_g  = (const float*)d_in[17];
    const float* ln2_b  = (const float*)d_in[18];
    const float* proj_w = (const float*)d_in[19];
    const float* proj_b = (const float*)d_in[20];
    float* out = (float*)d_out;

    float *ph, *pctx, *pt1, *pt2, *pwt;
    cudaGetSymbolAddress((void**)&ph,   g_h);
    cudaGetSymbolAddress((void**)&pctx, g_ctx);
    cudaGetSymbolAddress((void**)&pt1,  g_t1);
    cudaGetSymbolAddress((void**)&pt2,  g_t2);
    cudaGetSymbolAddress((void**)&pwt,  g_wt);

    const int GEMM_SMEM   = 2*GSTAGE*GBUF*sizeof(float);       // 110592
    const int MSTATS_SMEM = (3*QTILE + 1024)*sizeof(float);    // 108544
    const int ATT_SMEM    = ATT_SMEM_FLOATS*sizeof(float);     // 102112
    cudaFuncSetAttribute(gemm_mma,   cudaFuncAttributeMaxDynamicSharedMemorySize, GEMM_SMEM);
    cudaFuncSetAttribute(gemm_qkv,   cudaFuncAttributeMaxDynamicSharedMemorySize, GEMM_SMEM);
    cudaFuncSetAttribute(mstats_mma, cudaFuncAttributeMaxDynamicSharedMemorySize, MSTATS_SMEM);
    cudaFuncSetAttribute(attn_part,  cudaFuncAttributeMaxDynamicSharedMemorySize, ATT_SMEM);

    transpose_all<<<dim3(16, 16, 12), dim3(32, 8)>>>(Wq, Wk, Wv, Wo, W1, W2);
    embed_kernel<<<dim3(BL, DD/256), 256>>>(x, emb_w, emb_b);

    dim3 ggrid(DD/128, BL/128);       // (4, 64)

    for (int lay = 0; lay < NLL; lay++) {
        float* tWo = pwt + (size_t)(lay*6 + 3)*DD*DD;
        float* tW1 = pwt + (size_t)(lay*6 + 4)*DD*DD;
        float* tW2 = pwt + (size_t)(lay*6 + 5)*DD*DD;

        gemm_qkv<<<dim3(DD/128, BL/128, 3), 256, GEMM_SMEM>>>(
            lay, bq + lay*DD, bk + lay*DD, bv + lay*DD);

        mstats_mma<<<dim3(LL/128, BB*HH), 256, MSTATS_SMEM>>>();
        topk_kernel<<<BB*HH, 256>>>();

        attn_part<<<dim3(ASPLIT, BB*HH), 256, ATT_SMEM>>>();
        vmean_combine<<<BB*HH, 64>>>();
        ctx_fill_kernel<<<dim3(BL, DD/256), 256>>>();
        attn_combine<<<BB*HH, 256>>>();

        gemm_mma<<<ggrid, 256, GEMM_SMEM>>>(pctx, tWo, bo + lay*DD, pt1, 0);
        lnres_kernel<<<BL, 256>>>(pt1, ln1_g + lay*DD, ln1_b + lay*DD);

        gemm_mma<<<ggrid, 256, GEMM_SMEM>>>(ph, tW1, b1 + lay*DD, pt1, 1);
        gemm_mma<<<ggrid, 256, GEMM_SMEM>>>(pt1, tW2, b2 + lay*DD, pt2, 0);
        lnres_kernel<<<BL, 256>>>(pt2, ln2_g + lay*DD, ln2_b + lay*DD);
    }

    proj_kernel<<<BB*PP, 256>>>(proj_w, proj_b, out);
}